// round 8
// baseline (speedup 1.0000x reference)
#include <cuda_runtime.h>
#include <cuda_fp16.h>

typedef unsigned long long ull;
typedef unsigned int u32;

constexpr int cNU = 4096, cNV = 4096, cD = 256, cH = 64, cR = 5, cB = 4096;
constexpr int KSPLIT = 8;
constexpr int NPART = KSPLIT * cR;    // 40 partials per output matrix
constexpr int KSLICE = 4096 / KSPLIT; // 512
constexpr int NC = KSLICE / 64;       // 8 chunks (BK=64) per block

// ---------------- device scratch ----------------
__device__ float g_row[cR * cNU];
__device__ float g_col[cR * cNV];
__device__ float g_cinv[cR * cNU];
__device__ float g_rinv[cR * cNV];
__device__ float g_uw[cR * cD * cH];
__device__ float g_vw[cR * cD * cH];
// fp16 hi/lo images (scale*256 folded): side 0 = tv-side (A_u), side 1 = tu-side (A_v)
// layout: [side*5+r][k=4096][32 u32 along h]
__device__ u32 g_Bhi[2 * 5 * 131072];
__device__ u32 g_Blo[2 * 5 * 131072];
__device__ float g_pu[(size_t)NPART * cNU * cH];
__device__ float g_pv[(size_t)NPART * cNV * cH];
__device__ float g_Au[cNU * cH];
__device__ float g_Av[cNV * cH];

// ---------------- helpers ----------------
__device__ __forceinline__ u32 smem_u32(const void* p) {
    u32 a;
    asm("{ .reg .u64 t; cvta.to.shared.u64 t, %1; cvt.u32.u64 %0, t; }" : "=r"(a) : "l"(p));
    return a;
}
// fp16 split of a float pair: h = fp16x2(x0,x1), l = fp16x2 of residuals
__device__ __forceinline__ void split2h(float x0, float x1, u32 &h, u32 &l) {
    __half2 hh = __float22half2_rn(make_float2(x0, x1));
    float2 bk = __half22float2(hh);
    __half2 ll = __float22half2_rn(make_float2(x0 - bk.x, x1 - bk.y));
    h = *(u32*)&hh;
    l = *(u32*)&ll;
}
// fp16 hi-only pack
__device__ __forceinline__ u32 pack2h(float x0, float x1) {
    __half2 hh = __float22half2_rn(make_float2(x0, x1));
    return *(u32*)&hh;
}

#define LDSM4(r0, r1, r2, r3, addr) \
    asm volatile("ldmatrix.sync.aligned.m8n8.x4.shared.b16 {%0,%1,%2,%3}, [%4];" \
                 : "=r"(r0), "=r"(r1), "=r"(r2), "=r"(r3) : "r"(addr))
#define LDSM4T(r0, r1, r2, r3, addr) \
    asm volatile("ldmatrix.sync.aligned.m8n8.x4.trans.shared.b16 {%0,%1,%2,%3}, [%4];" \
                 : "=r"(r0), "=r"(r1), "=r"(r2), "=r"(r3) : "r"(addr))
#define MMA_F16(c, a0, a1, a2, a3, b0, b1) \
    asm volatile("mma.sync.aligned.m16n8k16.row.col.f32.f16.f16.f32 " \
                 "{%0,%1,%2,%3}, {%4,%5,%6,%7}, {%8,%9}, {%0,%1,%2,%3};" \
                 : "+f"((c)[0]), "+f"((c)[1]), "+f"((c)[2]), "+f"((c)[3]) \
                 : "r"(a0), "r"(a1), "r"(a2), "r"(a3), "r"(b0), "r"(b1))
#define CP_ASYNC16(smaddr, gptr) \
    asm volatile("cp.async.ca.shared.global [%0], [%1], 16;" :: "r"(smaddr), "l"(gptr))
#define CP_COMMIT() asm volatile("cp.async.commit_group;" ::: "memory")
#define CP_WAIT0()  asm volatile("cp.async.wait_group 0;" ::: "memory")

// smem swizzles (byte offsets; writer and ldmatrix reader use the same formula)
__device__ __forceinline__ u32 swzA_nt(int row, int k) {   // [128][64] fp16, 128B rows
    u32 o = (u32)(row * 128 + k * 2); return o ^ ((o >> 3) & 0x70);
}
__device__ __forceinline__ u32 swzA_t(int k, int row) {    // [64][128] fp16, 256B rows
    u32 o = (u32)(k * 256 + row * 2); return o ^ ((o >> 4) & 0x70);
}
__device__ __forceinline__ u32 swzB(int k, int n) {        // [64][64] fp16, 128B rows
    u32 o = (u32)(k * 128 + n * 2); return o ^ ((o >> 3) & 0x70);
}

// ---------------- f32x2 helpers for kfeat ----------------
__device__ __forceinline__ ull dupf(float x) {
    ull r; asm("mov.b64 %0, {%1, %1};" : "=l"(r) : "f"(x)); return r;
}
__device__ __forceinline__ void ffma2(ull &d, ull a, ull b) {
    asm("fma.rn.f32x2 %0, %1, %2, %0;" : "+l"(d) : "l"(a), "l"(b));
}
union U2 { ull u; float2 f; };

// ---------------- tiny kernels ----------------
__global__ void kzero() {
    int i = blockIdx.x * blockDim.x + threadIdx.x;
    if (i < cR * cNU) { g_row[i] = 0.f; g_col[i] = 0.f; }
}

__global__ void kcumsum(const float* __restrict__ uw, const float* __restrict__ vw) {
    int i = blockIdx.x * blockDim.x + threadIdx.x;
    if (i >= cD * cH) return;
    float a = 0.f, b = 0.f;
#pragma unroll
    for (int r = 0; r < cR; r++) {
        a += uw[r * cD * cH + i]; g_uw[r * cD * cH + i] = a;
        b += vw[r * cD * cH + i]; g_vw[r * cD * cH + i] = b;
    }
}

__global__ void __launch_bounds__(256) ksums(const float* __restrict__ S) {
    constexpr int RPC = 32;
    int blk = blockIdx.x;
    int r  = blk / (cNU / RPC);
    int n0 = (blk % (cNU / RPC)) * RPC;
    const float* base = S + ((size_t)r * cNU + n0) * cNV;
    int t = threadIdx.x;
    float4 c0 = {0,0,0,0}, c1 = c0, c2 = c0, c3 = c0;
    for (int i = 0; i < RPC; i++) {
        const float4* rp = (const float4*)(base + (size_t)i * cNV);
        float4 v0 = rp[t], v1 = rp[t + 256], v2 = rp[t + 512], v3 = rp[t + 768];
        c0.x += v0.x; c0.y += v0.y; c0.z += v0.z; c0.w += v0.w;
        c1.x += v1.x; c1.y += v1.y; c1.z += v1.z; c1.w += v1.w;
        c2.x += v2.x; c2.y += v2.y; c2.z += v2.z; c2.w += v2.w;
        c3.x += v3.x; c3.y += v3.y; c3.z += v3.z; c3.w += v3.w;
        float rs = v0.x + v0.y + v0.z + v0.w + v1.x + v1.y + v1.z + v1.w
                 + v2.x + v2.y + v2.z + v2.w + v3.x + v3.y + v3.z + v3.w;
#pragma unroll
        for (int o = 16; o > 0; o >>= 1) rs += __shfl_down_sync(0xffffffffu, rs, o);
        if ((t & 31) == 0) atomicAdd(&g_row[r * cNU + n0 + i], rs);
    }
    float* col = g_col + r * cNV;
    int c = 4 * t;
    atomicAdd(&col[c+0],    c0.x); atomicAdd(&col[c+1],    c0.y);
    atomicAdd(&col[c+2],    c0.z); atomicAdd(&col[c+3],    c0.w);
    atomicAdd(&col[c+1024], c1.x); atomicAdd(&col[c+1025], c1.y);
    atomicAdd(&col[c+1026], c1.z); atomicAdd(&col[c+1027], c1.w);
    atomicAdd(&col[c+2048], c2.x); atomicAdd(&col[c+2049], c2.y);
    atomicAdd(&col[c+2050], c2.z); atomicAdd(&col[c+2051], c2.w);
    atomicAdd(&col[c+3072], c3.x); atomicAdd(&col[c+3073], c3.y);
    atomicAdd(&col[c+3074], c3.z); atomicAdd(&col[c+3075], c3.w);
}

__global__ void kinv() {
    int i = blockIdx.x * blockDim.x + threadIdx.x;
    if (i >= cR * cNU) return;
    float x = g_row[i]; g_cinv[i] = x > 0.f ? rsqrtf(x) : 0.f;
    float y = g_col[i]; g_rinv[i] = y > 0.f ? rsqrtf(y) : 0.f;
}

// ---------------- feature GEMM, epilogue writes scaled fp16 hi/lo images ----
__device__ __forceinline__ void micro_nt(const float* __restrict__ sA,
                                         const float* __restrict__ sB,
                                         int lane, int hg, ull (&acc)[4][4]) {
#pragma unroll
    for (int k4 = 0; k4 < 32; k4 += 4) {
        float4 a[4];
#pragma unroll
        for (int i = 0; i < 4; i++) a[i] = *(const float4*)(sA + (lane + 32 * i) * 36 + k4);
#pragma unroll
        for (int kk = 0; kk < 4; kk++) {
            const float* bp = sB + (k4 + kk) * 64 + hg * 8;
            longlong2 bA = *(const longlong2*)bp;
            longlong2 bB = *(const longlong2*)(bp + 4);
#pragma unroll
            for (int i = 0; i < 4; i++) {
                float av = (kk == 0) ? a[i].x : (kk == 1) ? a[i].y : (kk == 2) ? a[i].z : a[i].w;
                ull ad = dupf(av);
                ffma2(acc[i][0], ad, (ull)bA.x);
                ffma2(acc[i][1], ad, (ull)bA.y);
                ffma2(acc[i][2], ad, (ull)bB.x);
                ffma2(acc[i][3], ad, (ull)bB.y);
            }
        }
    }
}

__global__ void __launch_bounds__(256, 2) kfeat(const float* __restrict__ u_feat,
                                                const float* __restrict__ v_feat) {
    __shared__ float sA[128 * 36];
    __shared__ float sB[32 * 64];
    int sid = blockIdx.y;
    bool uside = sid < cR;
    int r = uside ? sid : sid - cR;
    const float* F  = uside ? u_feat : v_feat;
    const float* W  = (uside ? g_uw : g_vw) + r * cD * cH;
    const float* sv = (uside ? g_cinv : g_rinv) + r * 4096;
    const size_t ib = (size_t)((uside ? 5 + r : r)) * 131072;
    int t = threadIdx.x, lane = t & 31, hg = t >> 5;
    int outb = blockIdx.x * 128;
    ull acc[4][4];
#pragma unroll
    for (int i = 0; i < 4; i++)
#pragma unroll
        for (int j = 0; j < 4; j++) acc[i][j] = 0ull;
    for (int kb = 0; kb < cD; kb += 32) {
#pragma unroll
        for (int q = 0; q < 2; q++) {
            int fi = t + q * 256;
            int kr = fi >> 4, c4 = (fi & 15) * 4;
            *(float4*)(sB + kr * 64 + c4) = *(const float4*)(W + (kb + kr) * 64 + c4);
        }
#pragma unroll
        for (int q = 0; q < 4; q++) {
            int fi = t + q * 256;
            int row = fi >> 3, c4 = (fi & 7) * 4;
            *(float4*)(sA + row * 36 + c4) = *(const float4*)(F + (size_t)(outb + row) * cD + kb + c4);
        }
        __syncthreads();
        micro_nt(sA, sB, lane, hg, acc);
        __syncthreads();
    }
#pragma unroll
    for (int i = 0; i < 4; i++) {
        int row = outb + lane + 32 * i;
        float s = sv[row] * 256.f;   // pre-scale by 256 to keep fp16 lo normal
        U2 w0, w1, w2, w3;
        w0.u = acc[i][0]; w1.u = acc[i][1]; w2.u = acc[i][2]; w3.u = acc[i][3];
        float f[8] = {w0.f.x, w0.f.y, w1.f.x, w1.f.y, w2.f.x, w2.f.y, w3.f.x, w3.f.y};
        size_t o = ib + (size_t)row * 32 + hg * 4;
#pragma unroll
        for (int j = 0; j < 4; j++) {
            u32 h, l;
            split2h(s * f[2 * j], s * f[2 * j + 1], h, l);
            g_Bhi[o + j] = h;
            g_Blo[o + j] = l;
        }
    }
}

// ---------------- main contraction: fp16 2-term (Ahi*Bhi + Ahi*Blo) ----------
// smem per buf (32 KB): Ahi @0 (16K), Bhi @16384 (8K), Blo @24576 (8K)
template <bool TRANS>
__device__ __forceinline__ void kmain_body(const float* __restrict__ S,
                                           unsigned char (*sm)[32768],
                                           int r, int tileb, int ks) {
    const int t = threadIdx.x;
    const int wid = t >> 5, lane = t & 31;
    const float* Sr = S + (size_t)r * cNU * cNV;
    const float* svec = (TRANS ? g_rinv : g_cinv) + r * 4096;
    const int sr = (TRANS ? 5 : 0) + r;
    const u32* imgh = g_Bhi + (size_t)sr * 131072;
    const u32* imgl = g_Blo + (size_t)sr * 131072;
    const int kbase = ks * KSLICE;
    const u32 sb = smem_u32(sm);

    float acc[8][4];
#pragma unroll
    for (int j = 0; j < 8; j++)
#pragma unroll
        for (int q = 0; q < 4; q++) acc[j][q] = 0.f;

    float4 ra[8];
    auto ldgA = [&](int c) {
        if (!TRANS) {
            const float4* ap =
                (const float4*)(Sr + (size_t)(tileb + (t >> 1)) * 4096 + kbase + c * 64 + (t & 1) * 32);
#pragma unroll
            for (int i = 0; i < 8; i++) ra[i] = ap[i];
        } else {
            const float4* ap =
                (const float4*)(Sr + (size_t)(kbase + c * 64 + (t >> 2)) * 4096 + tileb + (t & 3) * 32);
#pragma unroll
            for (int i = 0; i < 8; i++) ra[i] = ap[i];
        }
    };
    auto stsA = [&](int b) {
        unsigned char* base = sm[b];
        const float* f = (const float*)ra;
        if (!TRANS) {
            int row = t >> 1, kk = (t & 1) * 32;
#pragma unroll
            for (int j = 0; j < 16; j++)
                *(u32*)(base + swzA_nt(row, kk + 2 * j)) = pack2h(f[2 * j], f[2 * j + 1]);
        } else {
            int k = t >> 2, rb = (t & 3) * 32;
#pragma unroll
            for (int j = 0; j < 16; j++)
                *(u32*)(base + swzA_t(k, rb + 2 * j)) = pack2h(f[2 * j], f[2 * j + 1]);
        }
    };
    auto cpB = [&](int c, int b) {
        const u32 sbuf = sb + b * 32768;
#pragma unroll
        for (int p = 0; p < 2; p++) {
            int krow = (t >> 3) + p * 32;
            u32 off = swzB(krow, (t & 7) * 8);
            size_t gofs = (size_t)(kbase + c * 64 + krow) * 32 + (t & 7) * 4;
            CP_ASYNC16(sbuf + 16384 + off, imgh + gofs);
            CP_ASYNC16(sbuf + 24576 + off, imgl + gofs);
        }
        CP_COMMIT();
    };

    // ---- prologue ----
    ldgA(0);
    cpB(0, 0);
    stsA(0);
    ldgA(1);

    for (int c = 0; c < NC; c++) {
        CP_WAIT0();
        __syncthreads();
        if (c + 1 < NC) {
            stsA((c + 1) & 1);
            cpB(c + 1, (c + 1) & 1);
            if (c + 2 < NC) ldgA(c + 2);
        }
        const u32 sbuf = sb + (c & 1) * 32768;
#pragma unroll
        for (int s = 0; s < 4; s++) {
            const int k0s = s * 16;
            u32 ah0, ah1, ah2, ah3;
            if (!TRANS) {
                u32 off = swzA_nt(wid * 16 + (lane & 15), (lane >> 4) * 8 + k0s);
                LDSM4(ah0, ah1, ah2, ah3, sbuf + off);
            } else {
                int krow = k0s + (lane & 7) + ((lane >> 4) << 3);
                int col = wid * 16 + ((lane >> 3) & 1) * 8;
                u32 off = swzA_t(krow, col);
                LDSM4T(ah0, ah1, ah2, ah3, sbuf + off);
            }
            u32 bh[4][4], bl[4][4];
            {
                int krow = k0s + (lane & 15);
#pragma unroll
                for (int g = 0; g < 4; g++) {
                    u32 off = swzB(krow, g * 16 + (lane >> 4) * 8);
                    LDSM4T(bh[g][0], bh[g][1], bh[g][2], bh[g][3], sbuf + 16384 + off);
                    LDSM4T(bl[g][0], bl[g][1], bl[g][2], bl[g][3], sbuf + 24576 + off);
                }
            }
#pragma unroll
            for (int g = 0; g < 4; g++) {
#pragma unroll
                for (int half = 0; half < 2; half++) {
                    const int j = 2 * g + half;
                    MMA_F16(acc[j], ah0, ah1, ah2, ah3, bh[g][2 * half], bh[g][2 * half + 1]);
                    MMA_F16(acc[j], ah0, ah1, ah2, ah3, bl[g][2 * half], bl[g][2 * half + 1]);
                }
            }
        }
    }

    const int g2 = lane >> 2, t2 = lane & 3;
    const int row0 = tileb + wid * 16 + g2;
    const int row1 = row0 + 8;
    const float s0 = svec[row0] * 0.00390625f;   // undo the 256x image pre-scale
    const float s1 = svec[row1] * 0.00390625f;
    float* P = (TRANS ? g_pv : g_pu) + (size_t)(ks * cR + r) * 4096 * 64;
#pragma unroll
    for (int j = 0; j < 8; j++) {
        const int col = j * 8 + 2 * t2;
        *(float2*)(P + (size_t)row0 * 64 + col) = make_float2(s0 * acc[j][0], s0 * acc[j][1]);
        *(float2*)(P + (size_t)row1 * 64 + col) = make_float2(s1 * acc[j][2], s1 * acc[j][3]);
    }
}

__global__ void __launch_bounds__(256, 2) kmain_all(const float* __restrict__ S) {
    __shared__ __align__(1024) unsigned char sm[2][32768];
    const int z = blockIdx.z;
    const int side = z / cR, r = z % cR;
    const int tileb = blockIdx.x * 128;
    const int ks = blockIdx.y;
    if (side == 0) kmain_body<false>(S, sm, r, tileb, ks);
    else           kmain_body<true >(S, sm, r, tileb, ks);
}

__global__ void kreduce() {
    int i = blockIdx.x * blockDim.x + threadIdx.x;
    if (i >= cNU * cH) return;
    float su = 0.f, sv = 0.f;
#pragma unroll 8
    for (int p = 0; p < NPART; p++) {
        su += g_pu[(size_t)p * cNU * cH + i];
        sv += g_pv[(size_t)p * cNV * cH + i];
    }
    g_Au[i] = su;
    g_Av[i] = sv;
}

__global__ void kout(const int* __restrict__ u, const int* __restrict__ v,
                     const float* __restrict__ bias, float* __restrict__ out) {
    int i = blockIdx.x * blockDim.x + threadIdx.x;
    if (i >= 2 * cB * cH) return;
    int h = i & 63;
    float bv = bias[h];
    float z;
    if (i < cB * cH) {
        int b = i >> 6;
        z = g_Au[(size_t)u[b] * cH + h] + bv;
    } else {
        int b = (i - cB * cH) >> 6;
        z = g_Av[(size_t)v[b] * cH + h] + bv;
    }
    out[i] = z > 0.f ? z : 0.f;
}

// ---------------- launch ----------------
extern "C" void kernel_launch(void* const* d_in, const int* in_sizes, int n_in,
                              void* d_out, int out_size) {
    const float* u_feat   = (const float*)d_in[0];
    const float* v_feat   = (const float*)d_in[1];
    const int*   u        = (const int*)d_in[2];
    const int*   v        = (const int*)d_in[3];
    const float* support  = (const float*)d_in[4];
    const float* u_weight = (const float*)d_in[5];
    const float* v_weight = (const float*)d_in[6];
    const float* u_bias   = (const float*)d_in[7];
    float* out = (float*)d_out;

    kzero<<<80, 256>>>();
    kcumsum<<<64, 256>>>(u_weight, v_weight);
    ksums<<<640, 256>>>(support);
    kinv<<<80, 256>>>();
    kfeat<<<dim3(32, 10), 256>>>(u_feat, v_feat);
    kmain_all<<<dim3(32, KSPLIT, 2 * cR), 256>>>(support);
    kreduce<<<1024, 256>>>();
    kout<<<2048, 256>>>(u, v, u_bias, out);
}

// round 9
// speedup vs baseline: 1.1842x; 1.1842x over previous
#include <cuda_runtime.h>
#include <cuda_fp16.h>

typedef unsigned long long ull;
typedef unsigned int u32;

constexpr int cNU = 4096, cNV = 4096, cD = 256, cH = 64, cR = 5, cB = 4096;
constexpr int KSPLIT = 8;
constexpr int NPART = KSPLIT * cR;    // 40 partials per output matrix
constexpr int KSLICE = 4096 / KSPLIT; // 512
constexpr int NC = KSLICE / 32;       // 16 chunks (BK=32) per block

// ---------------- device scratch ----------------
__device__ float g_row[cR * cNU];
__device__ float g_col[cR * cNV];
__device__ float g_cinv[cR * cNU];
__device__ float g_rinv[cR * cNV];
__device__ float g_uw[cR * cD * cH];
__device__ float g_vw[cR * cD * cH];
// fp16 hi/lo images (scale*256 folded): side 0 = tv-side (A_u), side 1 = tu-side (A_v)
// layout: [side*5+r][k=4096][32 u32 along h]
__device__ u32 g_Bhi[2 * 5 * 131072];
__device__ u32 g_Blo[2 * 5 * 131072];
__device__ float g_pu[(size_t)NPART * cNU * cH];
__device__ float g_pv[(size_t)NPART * cNV * cH];
__device__ float g_Au[cNU * cH];
__device__ float g_Av[cNV * cH];

// ---------------- helpers ----------------
__device__ __forceinline__ u32 smem_u32(const void* p) {
    u32 a;
    asm("{ .reg .u64 t; cvta.to.shared.u64 t, %1; cvt.u32.u64 %0, t; }" : "=r"(a) : "l"(p));
    return a;
}
// fp16 split of a float pair: h = fp16x2(x0,x1), l = fp16x2 of residuals
__device__ __forceinline__ void split2h(float x0, float x1, u32 &h, u32 &l) {
    __half2 hh = __float22half2_rn(make_float2(x0, x1));
    float2 bk = __half22float2(hh);
    __half2 ll = __float22half2_rn(make_float2(x0 - bk.x, x1 - bk.y));
    h = *(u32*)&hh;
    l = *(u32*)&ll;
}
// fp16 hi-only pack
__device__ __forceinline__ u32 pack2h(float x0, float x1) {
    __half2 hh = __float22half2_rn(make_float2(x0, x1));
    return *(u32*)&hh;
}

#define LDSM4(r0, r1, r2, r3, addr) \
    asm volatile("ldmatrix.sync.aligned.m8n8.x4.shared.b16 {%0,%1,%2,%3}, [%4];" \
                 : "=r"(r0), "=r"(r1), "=r"(r2), "=r"(r3) : "r"(addr))
#define LDSM4T(r0, r1, r2, r3, addr) \
    asm volatile("ldmatrix.sync.aligned.m8n8.x4.trans.shared.b16 {%0,%1,%2,%3}, [%4];" \
                 : "=r"(r0), "=r"(r1), "=r"(r2), "=r"(r3) : "r"(addr))
#define MMA_F16(c, a0, a1, a2, a3, b0, b1) \
    asm volatile("mma.sync.aligned.m16n8k16.row.col.f32.f16.f16.f32 " \
                 "{%0,%1,%2,%3}, {%4,%5,%6,%7}, {%8,%9}, {%0,%1,%2,%3};" \
                 : "+f"((c)[0]), "+f"((c)[1]), "+f"((c)[2]), "+f"((c)[3]) \
                 : "r"(a0), "r"(a1), "r"(a2), "r"(a3), "r"(b0), "r"(b1))
#define CP_ASYNC16(smaddr, gptr) \
    asm volatile("cp.async.ca.shared.global [%0], [%1], 16;" :: "r"(smaddr), "l"(gptr))
#define CP_COMMIT() asm volatile("cp.async.commit_group;" ::: "memory")
#define CP_WAIT0()  asm volatile("cp.async.wait_group 0;" ::: "memory")

// smem swizzles (byte offsets; writer and ldmatrix reader use the same formula)
__device__ __forceinline__ u32 swzA_nt(int row, int k) {   // [128][32] fp16, 64B rows
    u32 o = (u32)(row * 64 + k * 2); return o ^ ((o >> 3) & 0x30);
}
__device__ __forceinline__ u32 swzA_t(int k, int row) {    // [32][128] fp16, 256B rows
    u32 o = (u32)(k * 256 + row * 2); return o ^ ((o >> 4) & 0x70);
}
__device__ __forceinline__ u32 swzB(int k, int n) {        // [32][64] fp16, 128B rows
    u32 o = (u32)(k * 128 + n * 2); return o ^ ((o >> 3) & 0x70);
}

// ---------------- f32x2 helpers for kfeat ----------------
__device__ __forceinline__ ull dupf(float x) {
    ull r; asm("mov.b64 %0, {%1, %1};" : "=l"(r) : "f"(x)); return r;
}
__device__ __forceinline__ void ffma2(ull &d, ull a, ull b) {
    asm("fma.rn.f32x2 %0, %1, %2, %0;" : "+l"(d) : "l"(a), "l"(b));
}
union U2 { ull u; float2 f; };

// ---------------- tiny kernels ----------------
// fused: zero the sum buffers + cumsum the weights
__global__ void kinit(const float* __restrict__ uw, const float* __restrict__ vw) {
    int i = blockIdx.x * blockDim.x + threadIdx.x;
    if (i < cR * cNU) { g_row[i] = 0.f; g_col[i] = 0.f; }
    if (i < cD * cH) {
        float a = 0.f, b = 0.f;
#pragma unroll
        for (int r = 0; r < cR; r++) {
            a += uw[r * cD * cH + i]; g_uw[r * cD * cH + i] = a;
            b += vw[r * cD * cH + i]; g_vw[r * cD * cH + i] = b;
        }
    }
}

__global__ void __launch_bounds__(256) ksums(const float* __restrict__ S) {
    constexpr int RPC = 32;
    int blk = blockIdx.x;
    int r  = blk / (cNU / RPC);
    int n0 = (blk % (cNU / RPC)) * RPC;
    const float* base = S + ((size_t)r * cNU + n0) * cNV;
    int t = threadIdx.x;
    float4 c0 = {0,0,0,0}, c1 = c0, c2 = c0, c3 = c0;
    for (int i = 0; i < RPC; i++) {
        const float4* rp = (const float4*)(base + (size_t)i * cNV);
        float4 v0 = rp[t], v1 = rp[t + 256], v2 = rp[t + 512], v3 = rp[t + 768];
        c0.x += v0.x; c0.y += v0.y; c0.z += v0.z; c0.w += v0.w;
        c1.x += v1.x; c1.y += v1.y; c1.z += v1.z; c1.w += v1.w;
        c2.x += v2.x; c2.y += v2.y; c2.z += v2.z; c2.w += v2.w;
        c3.x += v3.x; c3.y += v3.y; c3.z += v3.z; c3.w += v3.w;
        float rs = v0.x + v0.y + v0.z + v0.w + v1.x + v1.y + v1.z + v1.w
                 + v2.x + v2.y + v2.z + v2.w + v3.x + v3.y + v3.z + v3.w;
#pragma unroll
        for (int o = 16; o > 0; o >>= 1) rs += __shfl_down_sync(0xffffffffu, rs, o);
        if ((t & 31) == 0) atomicAdd(&g_row[r * cNU + n0 + i], rs);
    }
    float* col = g_col + r * cNV;
    int c = 4 * t;
    atomicAdd(&col[c+0],    c0.x); atomicAdd(&col[c+1],    c0.y);
    atomicAdd(&col[c+2],    c0.z); atomicAdd(&col[c+3],    c0.w);
    atomicAdd(&col[c+1024], c1.x); atomicAdd(&col[c+1025], c1.y);
    atomicAdd(&col[c+1026], c1.z); atomicAdd(&col[c+1027], c1.w);
    atomicAdd(&col[c+2048], c2.x); atomicAdd(&col[c+2049], c2.y);
    atomicAdd(&col[c+2050], c2.z); atomicAdd(&col[c+2051], c2.w);
    atomicAdd(&col[c+3072], c3.x); atomicAdd(&col[c+3073], c3.y);
    atomicAdd(&col[c+3074], c3.z); atomicAdd(&col[c+3075], c3.w);
}

__global__ void kinv() {
    int i = blockIdx.x * blockDim.x + threadIdx.x;
    if (i >= cR * cNU) return;
    float x = g_row[i]; g_cinv[i] = x > 0.f ? rsqrtf(x) : 0.f;
    float y = g_col[i]; g_rinv[i] = y > 0.f ? rsqrtf(y) : 0.f;
}

// ---------------- feature GEMM, epilogue writes scaled fp16 hi/lo images ----
__device__ __forceinline__ void micro_nt(const float* __restrict__ sA,
                                         const float* __restrict__ sB,
                                         int lane, int hg, ull (&acc)[4][4]) {
#pragma unroll
    for (int k4 = 0; k4 < 32; k4 += 4) {
        float4 a[4];
#pragma unroll
        for (int i = 0; i < 4; i++) a[i] = *(const float4*)(sA + (lane + 32 * i) * 36 + k4);
#pragma unroll
        for (int kk = 0; kk < 4; kk++) {
            const float* bp = sB + (k4 + kk) * 64 + hg * 8;
            longlong2 bA = *(const longlong2*)bp;
            longlong2 bB = *(const longlong2*)(bp + 4);
#pragma unroll
            for (int i = 0; i < 4; i++) {
                float av = (kk == 0) ? a[i].x : (kk == 1) ? a[i].y : (kk == 2) ? a[i].z : a[i].w;
                ull ad = dupf(av);
                ffma2(acc[i][0], ad, (ull)bA.x);
                ffma2(acc[i][1], ad, (ull)bA.y);
                ffma2(acc[i][2], ad, (ull)bB.x);
                ffma2(acc[i][3], ad, (ull)bB.y);
            }
        }
    }
}

__global__ void __launch_bounds__(256, 2) kfeat(const float* __restrict__ u_feat,
                                                const float* __restrict__ v_feat) {
    __shared__ float sA[128 * 36];
    __shared__ float sB[32 * 64];
    int sid = blockIdx.y;
    bool uside = sid < cR;
    int r = uside ? sid : sid - cR;
    const float* F  = uside ? u_feat : v_feat;
    const float* W  = (uside ? g_uw : g_vw) + r * cD * cH;
    const float* sv = (uside ? g_cinv : g_rinv) + r * 4096;
    const size_t ib = (size_t)((uside ? 5 + r : r)) * 131072;
    int t = threadIdx.x, lane = t & 31, hg = t >> 5;
    int outb = blockIdx.x * 128;
    ull acc[4][4];
#pragma unroll
    for (int i = 0; i < 4; i++)
#pragma unroll
        for (int j = 0; j < 4; j++) acc[i][j] = 0ull;
    for (int kb = 0; kb < cD; kb += 32) {
#pragma unroll
        for (int q = 0; q < 2; q++) {
            int fi = t + q * 256;
            int kr = fi >> 4, c4 = (fi & 15) * 4;
            *(float4*)(sB + kr * 64 + c4) = *(const float4*)(W + (kb + kr) * 64 + c4);
        }
#pragma unroll
        for (int q = 0; q < 4; q++) {
            int fi = t + q * 256;
            int row = fi >> 3, c4 = (fi & 7) * 4;
            *(float4*)(sA + row * 36 + c4) = *(const float4*)(F + (size_t)(outb + row) * cD + kb + c4);
        }
        __syncthreads();
        micro_nt(sA, sB, lane, hg, acc);
        __syncthreads();
    }
#pragma unroll
    for (int i = 0; i < 4; i++) {
        int row = outb + lane + 32 * i;
        float s = sv[row] * 256.f;   // pre-scale by 256 keeps fp16 lo normal
        U2 w0, w1, w2, w3;
        w0.u = acc[i][0]; w1.u = acc[i][1]; w2.u = acc[i][2]; w3.u = acc[i][3];
        float f[8] = {w0.f.x, w0.f.y, w1.f.x, w1.f.y, w2.f.x, w2.f.y, w3.f.x, w3.f.y};
        size_t o = ib + (size_t)row * 32 + hg * 4;
#pragma unroll
        for (int j = 0; j < 4; j++) {
            u32 h, l;
            split2h(s * f[2 * j], s * f[2 * j + 1], h, l);
            g_Bhi[o + j] = h;
            g_Blo[o + j] = l;
        }
    }
}

// ---------------- main contraction: fp16 2-term (Ahi*Bhi + Ahi*Blo) ----------
// smem per buf (16 KB): Ahi @0 (8K), Bhi @8192 (4K), Blo @12288 (4K)
template <bool TRANS>
__device__ __forceinline__ void kmain_body(const float* __restrict__ S,
                                           unsigned char (*sm)[16384],
                                           int r, int tileb, int ks) {
    const int t = threadIdx.x;
    const int wid = t >> 5, lane = t & 31;
    const float* Sr = S + (size_t)r * cNU * cNV;
    const float* svec = (TRANS ? g_rinv : g_cinv) + r * 4096;
    const int sr = (TRANS ? 5 : 0) + r;
    const u32* imgh = g_Bhi + (size_t)sr * 131072;
    const u32* imgl = g_Blo + (size_t)sr * 131072;
    const int kbase = ks * KSLICE;
    const u32 sb = smem_u32(sm);

    const int bk_ = t >> 3, bc4 = (t & 7) * 4;
    const u32 offB = swzB(bk_, (t & 7) * 8);

    float acc[8][4];
#pragma unroll
    for (int j = 0; j < 8; j++)
#pragma unroll
        for (int q = 0; q < 4; q++) acc[j][q] = 0.f;

    float4 ra[4];
    auto ldgA = [&](int c) {
        if (!TRANS) {
            const float4* ap =
                (const float4*)(Sr + (size_t)(tileb + (t >> 1)) * 4096 + kbase + c * 32 + (t & 1) * 16);
            ra[0] = ap[0]; ra[1] = ap[1]; ra[2] = ap[2]; ra[3] = ap[3];
        } else {
            const float4* ap =
                (const float4*)(Sr + (size_t)(kbase + c * 32 + (t >> 3)) * 4096 + tileb + (t & 7) * 16);
            ra[0] = ap[0]; ra[1] = ap[1]; ra[2] = ap[2]; ra[3] = ap[3];
        }
    };
    auto stsA = [&](int b) {
        unsigned char* base = sm[b];
        const float* f = (const float*)ra;
        if (!TRANS) {
            int row = t >> 1, kk = (t & 1) * 16;
#pragma unroll
            for (int j = 0; j < 8; j++)
                *(u32*)(base + swzA_nt(row, kk + 2 * j)) = pack2h(f[2 * j], f[2 * j + 1]);
        } else {
            int k = t >> 3, rb = (t & 7) * 16;
#pragma unroll
            for (int j = 0; j < 8; j++)
                *(u32*)(base + swzA_t(k, rb + 2 * j)) = pack2h(f[2 * j], f[2 * j + 1]);
        }
    };
    auto cpB = [&](int c, int b) {
        const u32 sbuf = sb + b * 16384;
        size_t gofs = (size_t)(kbase + c * 32 + bk_) * 32 + bc4;
        CP_ASYNC16(sbuf + 8192 + offB, imgh + gofs);
        CP_ASYNC16(sbuf + 12288 + offB, imgl + gofs);
        CP_COMMIT();
    };

    // ---- prologue ----
    ldgA(0);
    cpB(0, 0);
    stsA(0);
    ldgA(1);

    for (int c = 0; c < NC; c++) {
        CP_WAIT0();
        __syncthreads();
        if (c + 1 < NC) {
            stsA((c + 1) & 1);
            cpB(c + 1, (c + 1) & 1);
            if (c + 2 < NC) ldgA(c + 2);
        }
        const u32 sbuf = sb + (c & 1) * 16384;
#pragma unroll
        for (int s = 0; s < 2; s++) {
            const int k0s = s * 16;
            u32 ah0, ah1, ah2, ah3;
            if (!TRANS) {
                u32 off = swzA_nt(wid * 16 + (lane & 15), (lane >> 4) * 8 + k0s);
                LDSM4(ah0, ah1, ah2, ah3, sbuf + off);
            } else {
                int krow = k0s + (lane & 7) + ((lane >> 4) << 3);
                int col = wid * 16 + ((lane >> 3) & 1) * 8;
                u32 off = swzA_t(krow, col);
                LDSM4T(ah0, ah1, ah2, ah3, sbuf + off);
            }
            u32 bh[4][4], bl[4][4];
            {
                int krow = k0s + (lane & 15);
#pragma unroll
                for (int g = 0; g < 4; g++) {
                    u32 off = swzB(krow, g * 16 + (lane >> 4) * 8);
                    LDSM4T(bh[g][0], bh[g][1], bh[g][2], bh[g][3], sbuf + 8192 + off);
                    LDSM4T(bl[g][0], bl[g][1], bl[g][2], bl[g][3], sbuf + 12288 + off);
                }
            }
#pragma unroll
            for (int g = 0; g < 4; g++) {
#pragma unroll
                for (int half = 0; half < 2; half++) {
                    const int j = 2 * g + half;
                    MMA_F16(acc[j], ah0, ah1, ah2, ah3, bh[g][2 * half], bh[g][2 * half + 1]);
                    MMA_F16(acc[j], ah0, ah1, ah2, ah3, bl[g][2 * half], bl[g][2 * half + 1]);
                }
            }
        }
    }

    const int g2 = lane >> 2, t2 = lane & 3;
    const int row0 = tileb + wid * 16 + g2;
    const int row1 = row0 + 8;
    const float s0 = svec[row0] * 0.00390625f;   // undo the 256x image pre-scale
    const float s1 = svec[row1] * 0.00390625f;
    float* P = (TRANS ? g_pv : g_pu) + (size_t)(ks * cR + r) * 4096 * 64;
#pragma unroll
    for (int j = 0; j < 8; j++) {
        const int col = j * 8 + 2 * t2;
        *(float2*)(P + (size_t)row0 * 64 + col) = make_float2(s0 * acc[j][0], s0 * acc[j][1]);
        *(float2*)(P + (size_t)row1 * 64 + col) = make_float2(s1 * acc[j][2], s1 * acc[j][3]);
    }
}

__global__ void __launch_bounds__(256, 2) kmain_all(const float* __restrict__ S) {
    __shared__ __align__(1024) unsigned char sm[2][16384];
    const int z = blockIdx.z;
    const int side = z / cR, r = z % cR;
    const int tileb = blockIdx.x * 128;
    const int ks = blockIdx.y;
    if (side == 0) kmain_body<false>(S, sm, r, tileb, ks);
    else           kmain_body<true >(S, sm, r, tileb, ks);
}

__global__ void kreduce() {
    int i = blockIdx.x * blockDim.x + threadIdx.x;
    if (i >= cNU * cH) return;
    float su = 0.f, sv = 0.f;
#pragma unroll 8
    for (int p = 0; p < NPART; p++) {
        su += g_pu[(size_t)p * cNU * cH + i];
        sv += g_pv[(size_t)p * cNV * cH + i];
    }
    g_Au[i] = su;
    g_Av[i] = sv;
}

__global__ void kout(const int* __restrict__ u, const int* __restrict__ v,
                     const float* __restrict__ bias, float* __restrict__ out) {
    int i = blockIdx.x * blockDim.x + threadIdx.x;
    if (i >= 2 * cB * cH) return;
    int h = i & 63;
    float bv = bias[h];
    float z;
    if (i < cB * cH) {
        int b = i >> 6;
        z = g_Au[(size_t)u[b] * cH + h] + bv;
    } else {
        int b = (i - cB * cH) >> 6;
        z = g_Av[(size_t)v[b] * cH + h] + bv;
    }
    out[i] = z > 0.f ? z : 0.f;
}

// ---------------- launch ----------------
extern "C" void kernel_launch(void* const* d_in, const int* in_sizes, int n_in,
                              void* d_out, int out_size) {
    const float* u_feat   = (const float*)d_in[0];
    const float* v_feat   = (const float*)d_in[1];
    const int*   u        = (const int*)d_in[2];
    const int*   v        = (const int*)d_in[3];
    const float* support  = (const float*)d_in[4];
    const float* u_weight = (const float*)d_in[5];
    const float* v_weight = (const float*)d_in[6];
    const float* u_bias   = (const float*)d_in[7];
    float* out = (float*)d_out;

    kinit<<<80, 256>>>(u_weight, v_weight);
    ksums<<<640, 256>>>(support);
    kinv<<<80, 256>>>();
    kfeat<<<dim3(32, 10), 256>>>(u_feat, v_feat);
    kmain_all<<<dim3(32, KSPLIT, 2 * cR), 256>>>(support);
    kreduce<<<1024, 256>>>();
    kout<<<2048, 256>>>(u, v, u_bias, out);
}

// round 10
// speedup vs baseline: 1.2743x; 1.0761x over previous
#include <cuda_runtime.h>
#include <cuda_fp16.h>

typedef unsigned long long ull;
typedef unsigned int u32;

constexpr int cNU = 4096, cNV = 4096, cD = 256, cH = 64, cR = 5, cB = 4096;
constexpr int KSPLIT = 8;
constexpr int NPART = KSPLIT * cR;    // 40 partials per output matrix
constexpr int KSLICE = 4096 / KSPLIT; // 512
constexpr int NC = KSLICE / 32;       // 16 chunks (BK=32) per block

// ---------------- device scratch ----------------
__device__ float g_row[cR * cNU];
__device__ float g_col[cR * cNV];
__device__ float g_cinv[cR * cNU];
__device__ float g_rinv[cR * cNV];
__device__ float g_uw[cR * cD * cH];
__device__ float g_vw[cR * cD * cH];
// fp16 hi/lo images (scale*256 folded): side 0 = tv-side (A_u), side 1 = tu-side (A_v)
// layout: [side*5+r][k=4096][32 u32 along h]
__device__ u32 g_Bhi[2 * 5 * 131072];
__device__ u32 g_Blo[2 * 5 * 131072];
__device__ float g_pu[(size_t)NPART * cNU * cH];
__device__ float g_pv[(size_t)NPART * cNV * cH];
__device__ float g_Au[cNU * cH];
__device__ float g_Av[cNV * cH];

// ---------------- helpers ----------------
__device__ __forceinline__ u32 smem_u32(const void* p) {
    u32 a;
    asm("{ .reg .u64 t; cvta.to.shared.u64 t, %1; cvt.u32.u64 %0, t; }" : "=r"(a) : "l"(p));
    return a;
}
__device__ __forceinline__ void split2h(float x0, float x1, u32 &h, u32 &l) {
    __half2 hh = __float22half2_rn(make_float2(x0, x1));
    float2 bk = __half22float2(hh);
    __half2 ll = __float22half2_rn(make_float2(x0 - bk.x, x1 - bk.y));
    h = *(u32*)&hh;
    l = *(u32*)&ll;
}
__device__ __forceinline__ u32 pack2h(float x0, float x1) {
    __half2 hh = __float22half2_rn(make_float2(x0, x1));
    return *(u32*)&hh;
}

#define LDSM4(r, addr) \
    asm volatile("ldmatrix.sync.aligned.m8n8.x4.shared.b16 {%0,%1,%2,%3}, [%4];" \
                 : "=r"((r)[0]), "=r"((r)[1]), "=r"((r)[2]), "=r"((r)[3]) : "r"(addr))
#define LDSM4T(r, addr) \
    asm volatile("ldmatrix.sync.aligned.m8n8.x4.trans.shared.b16 {%0,%1,%2,%3}, [%4];" \
                 : "=r"((r)[0]), "=r"((r)[1]), "=r"((r)[2]), "=r"((r)[3]) : "r"(addr))
#define MMA_F16(c, a, b0, b1) \
    asm volatile("mma.sync.aligned.m16n8k16.row.col.f32.f16.f16.f32 " \
                 "{%0,%1,%2,%3}, {%4,%5,%6,%7}, {%8,%9}, {%0,%1,%2,%3};" \
                 : "+f"((c)[0]), "+f"((c)[1]), "+f"((c)[2]), "+f"((c)[3]) \
                 : "r"((a)[0]), "r"((a)[1]), "r"((a)[2]), "r"((a)[3]), "r"(b0), "r"(b1))
#define CP_ASYNC16(smaddr, gptr) \
    asm volatile("cp.async.ca.shared.global [%0], [%1], 16;" :: "r"(smaddr), "l"(gptr))
#define CP_COMMIT() asm volatile("cp.async.commit_group;" ::: "memory")
#define CP_WAIT0()  asm volatile("cp.async.wait_group 0;" ::: "memory")
#define CP_WAIT1()  asm volatile("cp.async.wait_group 1;" ::: "memory")

// smem swizzles (byte offsets; writer and ldmatrix reader use the same formula)
__device__ __forceinline__ u32 swzA_nt(int row, int k) {   // [128][32] fp16, 64B rows
    u32 o = (u32)(row * 64 + k * 2); return o ^ ((o >> 3) & 0x30);
}
__device__ __forceinline__ u32 swzA_t(int k, int row) {    // [32][128] fp16, 256B rows
    u32 o = (u32)(k * 256 + row * 2); return o ^ ((o >> 4) & 0x70);
}
__device__ __forceinline__ u32 swzB(int k, int n) {        // [32][64] fp16, 128B rows
    u32 o = (u32)(k * 128 + n * 2); return o ^ ((o >> 3) & 0x70);
}

// ---------------- f32x2 helpers for kfeat ----------------
__device__ __forceinline__ ull dupf(float x) {
    ull r; asm("mov.b64 %0, {%1, %1};" : "=l"(r) : "f"(x)); return r;
}
__device__ __forceinline__ void ffma2(ull &d, ull a, ull b) {
    asm("fma.rn.f32x2 %0, %1, %2, %0;" : "+l"(d) : "l"(a), "l"(b));
}
union U2 { ull u; float2 f; };

// ---------------- tiny kernels ----------------
__global__ void kinit(const float* __restrict__ uw, const float* __restrict__ vw) {
    int i = blockIdx.x * blockDim.x + threadIdx.x;
    if (i < cR * cNU) { g_row[i] = 0.f; g_col[i] = 0.f; }
    if (i < cD * cH) {
        float a = 0.f, b = 0.f;
#pragma unroll
        for (int r = 0; r < cR; r++) {
            a += uw[r * cD * cH + i]; g_uw[r * cD * cH + i] = a;
            b += vw[r * cD * cH + i]; g_vw[r * cD * cH + i] = b;
        }
    }
}

__global__ void __launch_bounds__(256) ksums(const float* __restrict__ S) {
    constexpr int RPC = 32;
    int blk = blockIdx.x;
    int r  = blk / (cNU / RPC);
    int n0 = (blk % (cNU / RPC)) * RPC;
    const float* base = S + ((size_t)r * cNU + n0) * cNV;
    int t = threadIdx.x;
    float4 c0 = {0,0,0,0}, c1 = c0, c2 = c0, c3 = c0;
    for (int i = 0; i < RPC; i++) {
        const float4* rp = (const float4*)(base + (size_t)i * cNV);
        float4 v0 = rp[t], v1 = rp[t + 256], v2 = rp[t + 512], v3 = rp[t + 768];
        c0.x += v0.x; c0.y += v0.y; c0.z += v0.z; c0.w += v0.w;
        c1.x += v1.x; c1.y += v1.y; c1.z += v1.z; c1.w += v1.w;
        c2.x += v2.x; c2.y += v2.y; c2.z += v2.z; c2.w += v2.w;
        c3.x += v3.x; c3.y += v3.y; c3.z += v3.z; c3.w += v3.w;
        float rs = v0.x + v0.y + v0.z + v0.w + v1.x + v1.y + v1.z + v1.w
                 + v2.x + v2.y + v2.z + v2.w + v3.x + v3.y + v3.z + v3.w;
#pragma unroll
        for (int o = 16; o > 0; o >>= 1) rs += __shfl_down_sync(0xffffffffu, rs, o);
        if ((t & 31) == 0) atomicAdd(&g_row[r * cNU + n0 + i], rs);
    }
    float* col = g_col + r * cNV;
    int c = 4 * t;
    atomicAdd(&col[c+0],    c0.x); atomicAdd(&col[c+1],    c0.y);
    atomicAdd(&col[c+2],    c0.z); atomicAdd(&col[c+3],    c0.w);
    atomicAdd(&col[c+1024], c1.x); atomicAdd(&col[c+1025], c1.y);
    atomicAdd(&col[c+1026], c1.z); atomicAdd(&col[c+1027], c1.w);
    atomicAdd(&col[c+2048], c2.x); atomicAdd(&col[c+2049], c2.y);
    atomicAdd(&col[c+2050], c2.z); atomicAdd(&col[c+2051], c2.w);
    atomicAdd(&col[c+3072], c3.x); atomicAdd(&col[c+3073], c3.y);
    atomicAdd(&col[c+3074], c3.z); atomicAdd(&col[c+3075], c3.w);
}

__global__ void kinv() {
    int i = blockIdx.x * blockDim.x + threadIdx.x;
    if (i >= cR * cNU) return;
    float x = g_row[i]; g_cinv[i] = x > 0.f ? rsqrtf(x) : 0.f;
    float y = g_col[i]; g_rinv[i] = y > 0.f ? rsqrtf(y) : 0.f;
}

// ---------------- feature GEMM (cp.async double-buffered FFMA2) ----------
__device__ __forceinline__ void micro_nt(const float* __restrict__ sA,
                                         const float* __restrict__ sB,
                                         int lane, int hg, ull (&acc)[4][4]) {
#pragma unroll
    for (int k4 = 0; k4 < 32; k4 += 4) {
        float4 a[4];
#pragma unroll
        for (int i = 0; i < 4; i++) a[i] = *(const float4*)(sA + (lane + 32 * i) * 36 + k4);
#pragma unroll
        for (int kk = 0; kk < 4; kk++) {
            const float* bp = sB + (k4 + kk) * 64 + hg * 8;
            longlong2 bA = *(const longlong2*)bp;
            longlong2 bB = *(const longlong2*)(bp + 4);
#pragma unroll
            for (int i = 0; i < 4; i++) {
                float av = (kk == 0) ? a[i].x : (kk == 1) ? a[i].y : (kk == 2) ? a[i].z : a[i].w;
                ull ad = dupf(av);
                ffma2(acc[i][0], ad, (ull)bA.x);
                ffma2(acc[i][1], ad, (ull)bA.y);
                ffma2(acc[i][2], ad, (ull)bB.x);
                ffma2(acc[i][3], ad, (ull)bB.y);
            }
        }
    }
}

__global__ void __launch_bounds__(256, 2) kfeat(const float* __restrict__ u_feat,
                                                const float* __restrict__ v_feat) {
    __shared__ float sA[2][128 * 36];
    __shared__ float sB[2][32 * 64];
    int sid = blockIdx.y;
    bool uside = sid < cR;
    int r = uside ? sid : sid - cR;
    const float* F  = uside ? u_feat : v_feat;
    const float* W  = (uside ? g_uw : g_vw) + r * cD * cH;
    const float* sv = (uside ? g_cinv : g_rinv) + r * 4096;
    const size_t ib = (size_t)((uside ? 5 + r : r)) * 131072;
    int t = threadIdx.x, lane = t & 31, hg = t >> 5;
    int outb = blockIdx.x * 128;
    const u32 sbA = smem_u32(sA), sbB = smem_u32(sB);

    auto cpTile = [&](int c, int b) {
        int kb = c * 32;
#pragma unroll
        for (int q = 0; q < 2; q++) {
            int fi = t + q * 256;
            int kr = fi >> 4, c4 = (fi & 15) * 4;
            CP_ASYNC16(sbB + b * 8192 + (kr * 64 + c4) * 4, W + (kb + kr) * 64 + c4);
        }
#pragma unroll
        for (int q = 0; q < 4; q++) {
            int fi = t + q * 256;
            int row = fi >> 3, c4 = (fi & 7) * 4;
            CP_ASYNC16(sbA + b * 18432 + (row * 36 + c4) * 4,
                       F + (size_t)(outb + row) * cD + kb + c4);
        }
        CP_COMMIT();
    };

    ull acc[4][4];
#pragma unroll
    for (int i = 0; i < 4; i++)
#pragma unroll
        for (int j = 0; j < 4; j++) acc[i][j] = 0ull;

    cpTile(0, 0);
    for (int c = 0; c < 8; c++) {
        if (c + 1 < 8) { cpTile(c + 1, (c + 1) & 1); CP_WAIT1(); }
        else           { CP_WAIT0(); }
        __syncthreads();
        micro_nt(sA[c & 1], sB[c & 1], lane, hg, acc);
        __syncthreads();
    }
#pragma unroll
    for (int i = 0; i < 4; i++) {
        int row = outb + lane + 32 * i;
        float s = sv[row] * 256.f;   // pre-scale by 256 keeps fp16 lo normal
        U2 w0, w1, w2, w3;
        w0.u = acc[i][0]; w1.u = acc[i][1]; w2.u = acc[i][2]; w3.u = acc[i][3];
        float f[8] = {w0.f.x, w0.f.y, w1.f.x, w1.f.y, w2.f.x, w2.f.y, w3.f.x, w3.f.y};
        size_t o = ib + (size_t)row * 32 + hg * 4;
#pragma unroll
        for (int j = 0; j < 4; j++) {
            u32 h, l;
            split2h(s * f[2 * j], s * f[2 * j + 1], h, l);
            g_Bhi[o + j] = h;
            g_Blo[o + j] = l;
        }
    }
}

// ---------------- main contraction: fp16 2-term, 32x32 warp tiles ----------
// smem per buf (16 KB): Ahi @0 (8K), Bhi @8192 (4K), Blo @12288 (4K)
template <bool TRANS>
__device__ __forceinline__ void kmain_body(const float* __restrict__ S,
                                           unsigned char (*sm)[16384],
                                           int r, int tileb, int ks) {
    const int t = threadIdx.x;
    const int wid = t >> 5, lane = t & 31;
    const int mw = (wid & 3) * 32;      // warp row base (0..96)
    const int nw = (wid >> 2) * 32;     // warp col base (0 or 32)
    const float* Sr = S + (size_t)r * cNU * cNV;
    const float* svec = (TRANS ? g_rinv : g_cinv) + r * 4096;
    const int sr = (TRANS ? 5 : 0) + r;
    const u32* imgh = g_Bhi + (size_t)sr * 131072;
    const u32* imgl = g_Blo + (size_t)sr * 131072;
    const int kbase = ks * KSLICE;
    const u32 sb = smem_u32(sm);

    const int bk_ = t >> 3, bc4 = (t & 7) * 4;
    const u32 offB = swzB(bk_, (t & 7) * 8);

    float acc[8][4];
#pragma unroll
    for (int j = 0; j < 8; j++)
#pragma unroll
        for (int q = 0; q < 4; q++) acc[j][q] = 0.f;

    float4 ra[4];
    auto ldgA = [&](int c) {
        if (!TRANS) {
            const float4* ap =
                (const float4*)(Sr + (size_t)(tileb + (t >> 1)) * 4096 + kbase + c * 32 + (t & 1) * 16);
            ra[0] = ap[0]; ra[1] = ap[1]; ra[2] = ap[2]; ra[3] = ap[3];
        } else {
            const float4* ap =
                (const float4*)(Sr + (size_t)(kbase + c * 32 + (t >> 3)) * 4096 + tileb + (t & 7) * 16);
            ra[0] = ap[0]; ra[1] = ap[1]; ra[2] = ap[2]; ra[3] = ap[3];
        }
    };
    auto stsA = [&](int b) {
        unsigned char* base = sm[b];
        const float* f = (const float*)ra;
        if (!TRANS) {
            int row = t >> 1, kk = (t & 1) * 16;
#pragma unroll
            for (int j = 0; j < 8; j++)
                *(u32*)(base + swzA_nt(row, kk + 2 * j)) = pack2h(f[2 * j], f[2 * j + 1]);
        } else {
            int k = t >> 3, rb = (t & 7) * 16;
#pragma unroll
            for (int j = 0; j < 8; j++)
                *(u32*)(base + swzA_t(k, rb + 2 * j)) = pack2h(f[2 * j], f[2 * j + 1]);
        }
    };
    auto cpB = [&](int c, int b) {
        const u32 sbuf = sb + b * 16384;
        size_t gofs = (size_t)(kbase + c * 32 + bk_) * 32 + bc4;
        CP_ASYNC16(sbuf + 8192 + offB, imgh + gofs);
        CP_ASYNC16(sbuf + 12288 + offB, imgl + gofs);
        CP_COMMIT();
    };

    // ---- prologue ----
    ldgA(0);
    cpB(0, 0);
    stsA(0);
    ldgA(1);

    for (int c = 0; c < NC; c++) {
        CP_WAIT0();
        __syncthreads();
        if (c + 1 < NC) {
            stsA((c + 1) & 1);
            cpB(c + 1, (c + 1) & 1);
            if (c + 2 < NC) ldgA(c + 2);
        }
        const u32 sbuf = sb + (c & 1) * 16384;
#pragma unroll
        for (int s = 0; s < 2; s++) {
            const int k0s = s * 16;
            u32 a[2][4];
            if (!TRANS) {
                int arow = mw + (lane & 15);
                int acol = (lane >> 4) * 8 + k0s;
                LDSM4(a[0], sbuf + swzA_nt(arow, acol));
                LDSM4(a[1], sbuf + swzA_nt(arow + 16, acol));
            } else {
                int krow = k0s + (lane & 7) + ((lane >> 4) << 3);
                int col0 = mw + ((lane >> 3) & 1) * 8;
                LDSM4T(a[0], sbuf + swzA_t(krow, col0));
                LDSM4T(a[1], sbuf + swzA_t(krow, col0 + 16));
            }
            u32 bh[2][4], bl[2][4];
            {
                int krow = k0s + (lane & 15);
#pragma unroll
                for (int g = 0; g < 2; g++) {
                    u32 off = swzB(krow, nw + g * 16 + (lane >> 4) * 8);
                    LDSM4T(bh[g], sbuf + 8192 + off);
                    LDSM4T(bl[g], sbuf + 12288 + off);
                }
            }
#pragma unroll
            for (int mi = 0; mi < 2; mi++)
#pragma unroll
                for (int g = 0; g < 2; g++)
#pragma unroll
                    for (int half = 0; half < 2; half++) {
                        const int j = mi * 4 + g * 2 + half;
                        MMA_F16(acc[j], a[mi], bh[g][2 * half], bh[g][2 * half + 1]);
                        MMA_F16(acc[j], a[mi], bl[g][2 * half], bl[g][2 * half + 1]);
                    }
        }
    }

    const int g2 = lane >> 2, t2 = lane & 3;
    float* P = (TRANS ? g_pv : g_pu) + (size_t)(ks * cR + r) * 4096 * 64;
#pragma unroll
    for (int mi = 0; mi < 2; mi++) {
        const int row0 = tileb + mw + mi * 16 + g2;
        const int row1 = row0 + 8;
        const float s0 = svec[row0] * 0.00390625f;   // undo 256x image pre-scale
        const float s1 = svec[row1] * 0.00390625f;
#pragma unroll
        for (int ni = 0; ni < 4; ni++) {
            const int j = mi * 4 + ni;
            const int col = nw + ni * 8 + 2 * t2;
            *(float2*)(P + (size_t)row0 * 64 + col) = make_float2(s0 * acc[j][0], s0 * acc[j][1]);
            *(float2*)(P + (size_t)row1 * 64 + col) = make_float2(s1 * acc[j][2], s1 * acc[j][3]);
        }
    }
}

__global__ void __launch_bounds__(256, 2) kmain_all(const float* __restrict__ S) {
    __shared__ __align__(1024) unsigned char sm[2][16384];
    const int z = blockIdx.z;
    const int side = z / cR, r = z % cR;
    const int tileb = blockIdx.x * 128;
    const int ks = blockIdx.y;
    if (side == 0) kmain_body<false>(S, sm, r, tileb, ks);
    else           kmain_body<true >(S, sm, r, tileb, ks);
}

__global__ void kreduce() {
    int i = blockIdx.x * blockDim.x + threadIdx.x;
    if (i >= cNU * cH) return;
    float su = 0.f, sv = 0.f;
#pragma unroll 8
    for (int p = 0; p < NPART; p++) {
        su += g_pu[(size_t)p * cNU * cH + i];
        sv += g_pv[(size_t)p * cNV * cH + i];
    }
    g_Au[i] = su;
    g_Av[i] = sv;
}

__global__ void kout(const int* __restrict__ u, const int* __restrict__ v,
                     const float* __restrict__ bias, float* __restrict__ out) {
    int i = blockIdx.x * blockDim.x + threadIdx.x;
    if (i >= 2 * cB * cH) return;
    int h = i & 63;
    float bv = bias[h];
    float z;
    if (i < cB * cH) {
        int b = i >> 6;
        z = g_Au[(size_t)u[b] * cH + h] + bv;
    } else {
        int b = (i - cB * cH) >> 6;
        z = g_Av[(size_t)v[b] * cH + h] + bv;
    }
    out[i] = z > 0.f ? z : 0.f;
}

// ---------------- launch ----------------
extern "C" void kernel_launch(void* const* d_in, const int* in_sizes, int n_in,
                              void* d_out, int out_size) {
    const float* u_feat   = (const float*)d_in[0];
    const float* v_feat   = (const float*)d_in[1];
    const int*   u        = (const int*)d_in[2];
    const int*   v        = (const int*)d_in[3];
    const float* support  = (const float*)d_in[4];
    const float* u_weight = (const float*)d_in[5];
    const float* v_weight = (const float*)d_in[6];
    const float* u_bias   = (const float*)d_in[7];
    float* out = (float*)d_out;

    kinit<<<80, 256>>>(u_weight, v_weight);
    ksums<<<640, 256>>>(support);
    kinv<<<80, 256>>>();
    kfeat<<<dim3(32, 10), 256>>>(u_feat, v_feat);
    kmain_all<<<dim3(32, KSPLIT, 2 * cR), 256>>>(support);
    kreduce<<<1024, 256>>>();
    kout<<<2048, 256>>>(u, v, u_bias, out);
}

// round 12
// speedup vs baseline: 1.3430x; 1.0539x over previous
#include <cuda_runtime.h>
#include <cuda_fp16.h>

typedef unsigned long long ull;
typedef unsigned int u32;

constexpr int cNU = 4096, cNV = 4096, cD = 256, cH = 64, cR = 5, cB = 4096;
constexpr int KSPLIT = 8;
constexpr int NPART = KSPLIT * cR;    // 40 partials per output matrix
constexpr int KSLICE = 4096 / KSPLIT; // 512
constexpr int NC = KSLICE / 32;       // 16 chunks (BK=32) per block

// ---------------- device scratch ----------------
__device__ float g_row[cR * cNU];
__device__ float g_col[cR * cNV];
// fp16 hi/lo images of cumsum'd weights * 256: [sid(0..9)][k=256][32 u32 along h]
__device__ u32 g_Wh[10 * 8192];
__device__ u32 g_Wl[10 * 8192];
// fp16 hi/lo images (scale*256 folded): side 0 = tv-side (A_u), side 1 = tu-side (A_v)
// layout: [side*5+r][k=4096][32 u32 along h]
__device__ u32 g_Bhi[2 * 5 * 131072];
__device__ u32 g_Blo[2 * 5 * 131072];
__device__ float g_pu[(size_t)NPART * cNU * cH];
__device__ float g_pv[(size_t)NPART * cNV * cH];
__device__ float g_Au[cNU * cH];
__device__ float g_Av[cNV * cH];

// ---------------- helpers ----------------
__device__ __forceinline__ u32 smem_u32(const void* p) {
    u32 a;
    asm("{ .reg .u64 t; cvta.to.shared.u64 t, %1; cvt.u32.u64 %0, t; }" : "=r"(a) : "l"(p));
    return a;
}
__device__ __forceinline__ void split2h(float x0, float x1, u32 &h, u32 &l) {
    __half2 hh = __float22half2_rn(make_float2(x0, x1));
    float2 bk = __half22float2(hh);
    __half2 ll = __float22half2_rn(make_float2(x0 - bk.x, x1 - bk.y));
    h = *(u32*)&hh;
    l = *(u32*)&ll;
}
__device__ __forceinline__ u32 pack2h(float x0, float x1) {
    __half2 hh = __float22half2_rn(make_float2(x0, x1));
    return *(u32*)&hh;
}
__device__ __forceinline__ float invs(float x) {
    return x > 0.f ? rsqrtf(x) : 0.f;
}

#define LDSM4(r, addr) \
    asm volatile("ldmatrix.sync.aligned.m8n8.x4.shared.b16 {%0,%1,%2,%3}, [%4];" \
                 : "=r"((r)[0]), "=r"((r)[1]), "=r"((r)[2]), "=r"((r)[3]) : "r"(addr))
#define LDSM4T(r, addr) \
    asm volatile("ldmatrix.sync.aligned.m8n8.x4.trans.shared.b16 {%0,%1,%2,%3}, [%4];" \
                 : "=r"((r)[0]), "=r"((r)[1]), "=r"((r)[2]), "=r"((r)[3]) : "r"(addr))
#define MMA_F16(c, a, b0, b1) \
    asm volatile("mma.sync.aligned.m16n8k16.row.col.f32.f16.f16.f32 " \
                 "{%0,%1,%2,%3}, {%4,%5,%6,%7}, {%8,%9}, {%0,%1,%2,%3};" \
                 : "+f"((c)[0]), "+f"((c)[1]), "+f"((c)[2]), "+f"((c)[3]) \
                 : "r"((a)[0]), "r"((a)[1]), "r"((a)[2]), "r"((a)[3]), "r"(b0), "r"(b1))
#define CP_ASYNC16(smaddr, gptr) \
    asm volatile("cp.async.ca.shared.global [%0], [%1], 16;" :: "r"(smaddr), "l"(gptr))
#define CP_COMMIT() asm volatile("cp.async.commit_group;" ::: "memory")
#define CP_WAIT0()  asm volatile("cp.async.wait_group 0;" ::: "memory")

// smem swizzles (byte offsets; writer and ldmatrix reader use the same formula)
__device__ __forceinline__ u32 swzA_nt(int row, int k) {   // [128][32] fp16, 64B rows
    u32 o = (u32)(row * 64 + k * 2); return o ^ ((o >> 3) & 0x30);
}
__device__ __forceinline__ u32 swzA_t(int k, int row) {    // [32][128] fp16, 256B rows
    u32 o = (u32)(k * 256 + row * 2); return o ^ ((o >> 4) & 0x70);
}
__device__ __forceinline__ u32 swzB(int k, int n) {        // [32][64] fp16, 128B rows
    u32 o = (u32)(k * 128 + n * 2); return o ^ ((o >> 3) & 0x70);
}

// ---------------- tiny kernels ----------------
// zero the sum buffers + cumsum the weights + split into fp16 hi/lo images (x256)
__global__ void kinit(const float* __restrict__ uw, const float* __restrict__ vw) {
    int i = blockIdx.x * blockDim.x + threadIdx.x;
    if (i < cR * cNU) { g_row[i] = 0.f; g_col[i] = 0.f; }
    if (i < cD * cH / 2) {          // 8192 h-pairs
        int k = i >> 5, hp = i & 31;
        float a0 = 0.f, a1 = 0.f, b0 = 0.f, b1 = 0.f;
#pragma unroll
        for (int r = 0; r < cR; r++) {
            a0 += uw[r * cD * cH + k * cH + 2 * hp];
            a1 += uw[r * cD * cH + k * cH + 2 * hp + 1];
            b0 += vw[r * cD * cH + k * cH + 2 * hp];
            b1 += vw[r * cD * cH + k * cH + 2 * hp + 1];
            u32 h, l;
            split2h(256.f * a0, 256.f * a1, h, l);
            g_Wh[(size_t)r * 8192 + k * 32 + hp] = h;
            g_Wl[(size_t)r * 8192 + k * 32 + hp] = l;
            split2h(256.f * b0, 256.f * b1, h, l);
            g_Wh[(size_t)(5 + r) * 8192 + k * 32 + hp] = h;
            g_Wl[(size_t)(5 + r) * 8192 + k * 32 + hp] = l;
        }
    }
}

__global__ void __launch_bounds__(256) ksums(const float* __restrict__ S) {
    constexpr int RPC = 32;
    int blk = blockIdx.x;
    int r  = blk / (cNU / RPC);
    int n0 = (blk % (cNU / RPC)) * RPC;
    const float* base = S + ((size_t)r * cNU + n0) * cNV;
    int t = threadIdx.x;
    float4 c0 = {0,0,0,0}, c1 = c0, c2 = c0, c3 = c0;
    for (int i = 0; i < RPC; i++) {
        const float4* rp = (const float4*)(base + (size_t)i * cNV);
        float4 v0 = rp[t], v1 = rp[t + 256], v2 = rp[t + 512], v3 = rp[t + 768];
        c0.x += v0.x; c0.y += v0.y; c0.z += v0.z; c0.w += v0.w;
        c1.x += v1.x; c1.y += v1.y; c1.z += v1.z; c1.w += v1.w;
        c2.x += v2.x; c2.y += v2.y; c2.z += v2.z; c2.w += v2.w;
        c3.x += v3.x; c3.y += v3.y; c3.z += v3.z; c3.w += v3.w;
        float rs = v0.x + v0.y + v0.z + v0.w + v1.x + v1.y + v1.z + v1.w
                 + v2.x + v2.y + v2.z + v2.w + v3.x + v3.y + v3.z + v3.w;
#pragma unroll
        for (int o = 16; o > 0; o >>= 1) rs += __shfl_down_sync(0xffffffffu, rs, o);
        if ((t & 31) == 0) atomicAdd(&g_row[r * cNU + n0 + i], rs);
    }
    float* col = g_col + r * cNV;
    int c = 4 * t;
    atomicAdd(&col[c+0],    c0.x); atomicAdd(&col[c+1],    c0.y);
    atomicAdd(&col[c+2],    c0.z); atomicAdd(&col[c+3],    c0.w);
    atomicAdd(&col[c+1024], c1.x); atomicAdd(&col[c+1025], c1.y);
    atomicAdd(&col[c+1026], c1.z); atomicAdd(&col[c+1027], c1.w);
    atomicAdd(&col[c+2048], c2.x); atomicAdd(&col[c+2049], c2.y);
    atomicAdd(&col[c+2050], c2.z); atomicAdd(&col[c+2051], c2.w);
    atomicAdd(&col[c+3072], c3.x); atomicAdd(&col[c+3073], c3.y);
    atomicAdd(&col[c+3074], c3.z); atomicAdd(&col[c+3075], c3.w);
}

// ---------------- feature GEMM on tensor cores (fp16 3-term split) ----------
// tile 128 x 64, K = 256 (8 chunks of BK=32), double buffered.
// smem per buf (24 KB): Fhi @0 (8K), Flo @8192 (8K), Whi @16384 (4K), Wlo @20480 (4K)
__global__ void __launch_bounds__(256, 2) kfeat(const float* __restrict__ u_feat,
                                                const float* __restrict__ v_feat) {
    __shared__ __align__(1024) unsigned char sm[2][24576];
    const int sid = blockIdx.y;
    const bool uside = sid < cR;
    const int r = uside ? sid : sid - cR;
    const float* F = uside ? u_feat : v_feat;
    const u32* Wh = g_Wh + (size_t)sid * 8192;   // sid == r (u) or 5+r (v)
    const u32* Wl = g_Wl + (size_t)sid * 8192;
    const float* sraw = (uside ? g_row : g_col) + r * 4096;
    const size_t ib = (size_t)(uside ? 5 + r : r) * 131072;  // output image side
    const int t = threadIdx.x;
    const int wid = t >> 5, lane = t & 31;
    const int mw = (wid & 3) * 32;
    const int nw = (wid >> 2) * 32;
    const int outb = blockIdx.x * 128;
    const u32 sb = smem_u32(sm);

    const int bk_ = t >> 3, bc4 = (t & 7) * 4;
    const u32 offB = swzB(bk_, (t & 7) * 8);

    float acc[8][4];
#pragma unroll
    for (int j = 0; j < 8; j++)
#pragma unroll
        for (int q = 0; q < 4; q++) acc[j][q] = 0.f;

    float4 ra[4];
    auto ldgF = [&](int c) {
        const float4* ap =
            (const float4*)(F + (size_t)(outb + (t >> 1)) * cD + c * 32 + (t & 1) * 16);
        ra[0] = ap[0]; ra[1] = ap[1]; ra[2] = ap[2]; ra[3] = ap[3];
    };
    auto stsF = [&](int b) {
        unsigned char* base = sm[b];
        const float* f = (const float*)ra;
        int row = t >> 1, kk = (t & 1) * 16;
#pragma unroll
        for (int j = 0; j < 8; j++) {
            u32 h, l; split2h(f[2 * j], f[2 * j + 1], h, l);
            u32 off = swzA_nt(row, kk + 2 * j);
            *(u32*)(base + off) = h;
            *(u32*)(base + 8192 + off) = l;
        }
    };
    auto cpW = [&](int c, int b) {
        const u32 sbuf = sb + b * 24576;
        size_t gofs = (size_t)(c * 32 + bk_) * 32 + bc4;
        CP_ASYNC16(sbuf + 16384 + offB, Wh + gofs);
        CP_ASYNC16(sbuf + 20480 + offB, Wl + gofs);
        CP_COMMIT();
    };

    ldgF(0);
    cpW(0, 0);
    stsF(0);
    ldgF(1);

    for (int c = 0; c < 8; c++) {
        CP_WAIT0();
        __syncthreads();
        if (c + 1 < 8) {
            stsF((c + 1) & 1);
            cpW(c + 1, (c + 1) & 1);
            if (c + 2 < 8) ldgF(c + 2);
        }
        const u32 sbuf = sb + (c & 1) * 24576;
#pragma unroll
        for (int s = 0; s < 2; s++) {
            const int k0s = s * 16;
            u32 ah[2][4], al[2][4];
            {
                int arow = mw + (lane & 15);
                int acol = (lane >> 4) * 8 + k0s;
                u32 o0 = swzA_nt(arow, acol), o1 = swzA_nt(arow + 16, acol);
                LDSM4(ah[0], sbuf + o0);
                LDSM4(ah[1], sbuf + o1);
                LDSM4(al[0], sbuf + 8192 + o0);
                LDSM4(al[1], sbuf + 8192 + o1);
            }
            u32 bh[2][4], bl[2][4];
            {
                int krow = k0s + (lane & 15);
#pragma unroll
                for (int g = 0; g < 2; g++) {
                    u32 off = swzB(krow, nw + g * 16 + (lane >> 4) * 8);
                    LDSM4T(bh[g], sbuf + 16384 + off);
                    LDSM4T(bl[g], sbuf + 20480 + off);
                }
            }
#pragma unroll
            for (int mi = 0; mi < 2; mi++)
#pragma unroll
                for (int g = 0; g < 2; g++)
#pragma unroll
                    for (int half = 0; half < 2; half++) {
                        const int j = mi * 4 + g * 2 + half;
                        MMA_F16(acc[j], ah[mi], bh[g][2 * half], bh[g][2 * half + 1]);
                        MMA_F16(acc[j], al[mi], bh[g][2 * half], bh[g][2 * half + 1]);
                        MMA_F16(acc[j], ah[mi], bl[g][2 * half], bl[g][2 * half + 1]);
                    }
        }
    }

    // epilogue: scale by rsqrt(sum) (x256 already folded into W images), split, store
    const int g2 = lane >> 2, t2 = lane & 3;
#pragma unroll
    for (int mi = 0; mi < 2; mi++) {
        const int row0 = outb + mw + mi * 16 + g2;
        const int row1 = row0 + 8;
        const float s0 = invs(sraw[row0]);
        const float s1 = invs(sraw[row1]);
#pragma unroll
        for (int ni = 0; ni < 4; ni++) {
            const int j = mi * 4 + ni;
            const int pair = (nw + ni * 8 + 2 * t2) >> 1;
            u32 h, l;
            split2h(s0 * acc[j][0], s0 * acc[j][1], h, l);
            g_Bhi[ib + (size_t)row0 * 32 + pair] = h;
            g_Blo[ib + (size_t)row0 * 32 + pair] = l;
            split2h(s1 * acc[j][2], s1 * acc[j][3], h, l);
            g_Bhi[ib + (size_t)row1 * 32 + pair] = h;
            g_Blo[ib + (size_t)row1 * 32 + pair] = l;
        }
    }
}

// ---------------- main contraction: fp16 2-term, 32x32 warp tiles ----------
// smem per buf (16 KB): Ahi @0 (8K), Bhi @8192 (4K), Blo @12288 (4K)
template <bool TRANS>
__device__ __forceinline__ void kmain_body(const float* __restrict__ S,
                                           unsigned char (*sm)[16384],
                                           int r, int tileb, int ks) {
    const int t = threadIdx.x;
    const int wid = t >> 5, lane = t & 31;
    const int mw = (wid & 3) * 32;      // warp row base (0..96)
    const int nw = (wid >> 2) * 32;     // warp col base (0 or 32)
    const float* Sr = S + (size_t)r * cNU * cNV;
    const float* sraw = (TRANS ? g_col : g_row) + r * 4096;
    const int sr = (TRANS ? 5 : 0) + r;
    const u32* imgh = g_Bhi + (size_t)sr * 131072;
    const u32* imgl = g_Blo + (size_t)sr * 131072;
    const int kbase = ks * KSLICE;
    const u32 sb = smem_u32(sm);

    const int bk_ = t >> 3, bc4 = (t & 7) * 4;
    const u32 offB = swzB(bk_, (t & 7) * 8);

    float acc[8][4];
#pragma unroll
    for (int j = 0; j < 8; j++)
#pragma unroll
        for (int q = 0; q < 4; q++) acc[j][q] = 0.f;

    float4 ra[4];
    auto ldgA = [&](int c) {
        if (!TRANS) {
            const float4* ap =
                (const float4*)(Sr + (size_t)(tileb + (t >> 1)) * 4096 + kbase + c * 32 + (t & 1) * 16);
            ra[0] = ap[0]; ra[1] = ap[1]; ra[2] = ap[2]; ra[3] = ap[3];
        } else {
            const float4* ap =
                (const float4*)(Sr + (size_t)(kbase + c * 32 + (t >> 3)) * 4096 + tileb + (t & 7) * 16);
            ra[0] = ap[0]; ra[1] = ap[1]; ra[2] = ap[2]; ra[3] = ap[3];
        }
    };
    auto stsA = [&](int b) {
        unsigned char* base = sm[b];
        const float* f = (const float*)ra;
        if (!TRANS) {
            int row = t >> 1, kk = (t & 1) * 16;
#pragma unroll
            for (int j = 0; j < 8; j++)
                *(u32*)(base + swzA_nt(row, kk + 2 * j)) = pack2h(f[2 * j], f[2 * j + 1]);
        } else {
            int k = t >> 3, rb = (t & 7) * 16;
#pragma unroll
            for (int j = 0; j < 8; j++)
                *(u32*)(base + swzA_t(k, rb + 2 * j)) = pack2h(f[2 * j], f[2 * j + 1]);
        }
    };
    auto cpB = [&](int c, int b) {
        const u32 sbuf = sb + b * 16384;
        size_t gofs = (size_t)(kbase + c * 32 + bk_) * 32 + bc4;
        CP_ASYNC16(sbuf + 8192 + offB, imgh + gofs);
        CP_ASYNC16(sbuf + 12288 + offB, imgl + gofs);
        CP_COMMIT();
    };

    // ---- prologue ----
    ldgA(0);
    cpB(0, 0);
    stsA(0);
    ldgA(1);

    for (int c = 0; c < NC; c++) {
        CP_WAIT0();
        __syncthreads();
        if (c + 1 < NC) {
            stsA((c + 1) & 1);
            cpB(c + 1, (c + 1) & 1);
            if (c + 2 < NC) ldgA(c + 2);
        }
        const u32 sbuf = sb + (c & 1) * 16384;
#pragma unroll
        for (int s = 0; s < 2; s++) {
            const int k0s = s * 16;
            u32 a[2][4];
            if (!TRANS) {
                int arow = mw + (lane & 15);
                int acol = (lane >> 4) * 8 + k0s;
                LDSM4(a[0], sbuf + swzA_nt(arow, acol));
                LDSM4(a[1], sbuf + swzA_nt(arow + 16, acol));
            } else {
                int krow = k0s + (lane & 7) + ((lane >> 4) << 3);
                int col0 = mw + ((lane >> 3) & 1) * 8;
                LDSM4T(a[0], sbuf + swzA_t(krow, col0));
                LDSM4T(a[1], sbuf + swzA_t(krow, col0 + 16));
            }
            u32 bh[2][4], bl[2][4];
            {
                int krow = k0s + (lane & 15);
#pragma unroll
                for (int g = 0; g < 2; g++) {
                    u32 off = swzB(krow, nw + g * 16 + (lane >> 4) * 8);
                    LDSM4T(bh[g], sbuf + 8192 + off);
                    LDSM4T(bl[g], sbuf + 12288 + off);
                }
            }
#pragma unroll
            for (int mi = 0; mi < 2; mi++)
#pragma unroll
                for (int g = 0; g < 2; g++)
#pragma unroll
                    for (int half = 0; half < 2; half++) {
                        const int j = mi * 4 + g * 2 + half;
                        MMA_F16(acc[j], a[mi], bh[g][2 * half], bh[g][2 * half + 1]);
                        MMA_F16(acc[j], a[mi], bl[g][2 * half], bl[g][2 * half + 1]);
                    }
        }
    }

    const int g2 = lane >> 2, t2 = lane & 3;
    float* P = (TRANS ? g_pv : g_pu) + (size_t)(ks * cR + r) * 4096 * 64;
#pragma unroll
    for (int mi = 0; mi < 2; mi++) {
        const int row0 = tileb + mw + mi * 16 + g2;
        const int row1 = row0 + 8;
        const float s0 = invs(sraw[row0]) * 0.00390625f;  // undo 256x image pre-scale
        const float s1 = invs(sraw[row1]) * 0.00390625f;
#pragma unroll
        for (int ni = 0; ni < 4; ni++) {
            const int j = mi * 4 + ni;
            const int col = nw + ni * 8 + 2 * t2;
            *(float2*)(P + (size_t)row0 * 64 + col) = make_float2(s0 * acc[j][0], s0 * acc[j][1]);
            *(float2*)(P + (size_t)row1 * 64 + col) = make_float2(s1 * acc[j][2], s1 * acc[j][3]);
        }
    }
}

__global__ void __launch_bounds__(256, 2) kmain_all(const float* __restrict__ S) {
    __shared__ __align__(1024) unsigned char sm[2][16384];
    const int z = blockIdx.z;
    const int side = z / cR, r = z % cR;
    const int tileb = blockIdx.x * 128;
    const int ks = blockIdx.y;
    if (side == 0) kmain_body<false>(S, sm, r, tileb, ks);
    else           kmain_body<true >(S, sm, r, tileb, ks);
}

__global__ void kreduce() {
    int i = blockIdx.x * blockDim.x + threadIdx.x;
    if (i >= cNU * cH) return;
    float su = 0.f, sv = 0.f;
#pragma unroll 8
    for (int p = 0; p < NPART; p++) {
        su += g_pu[(size_t)p * cNU * cH + i];
        sv += g_pv[(size_t)p * cNV * cH + i];
    }
    g_Au[i] = su;
    g_Av[i] = sv;
}

__global__ void kout(const int* __restrict__ u, const int* __restrict__ v,
                     const float* __restrict__ bias, float* __restrict__ out) {
    int i = blockIdx.x * blockDim.x + threadIdx.x;
    if (i >= 2 * cB * cH) return;
    int h = i & 63;
    float bv = bias[h];
    float z;
    if (i < cB * cH) {
        int b = i >> 6;
        z = g_Au[(size_t)u[b] * cH + h] + bv;
    } else {
        int b = (i - cB * cH) >> 6;
        z = g_Av[(size_t)v[b] * cH + h] + bv;
    }
    out[i] = z > 0.f ? z : 0.f;
}

// ---------------- launch ----------------
extern "C" void kernel_launch(void* const* d_in, const int* in_sizes, int n_in,
                              void* d_out, int out_size) {
    const float* u_feat   = (const float*)d_in[0];
    const float* v_feat   = (const float*)d_in[1];
    const int*   u        = (const int*)d_in[2];
    const int*   v        = (const int*)d_in[3];
    const float* support  = (const float*)d_in[4];
    const float* u_weight = (const float*)d_in[5];
    const float* v_weight = (const float*)d_in[6];
    const float* u_bias   = (const float*)d_in[7];
    float* out = (float*)d_out;

    kinit<<<80, 256>>>(u_weight, v_weight);
    ksums<<<640, 256>>>(support);
    kfeat<<<dim3(32, 10), 256>>>(u_feat, v_feat);
    kmain_all<<<dim3(32, KSPLIT, 2 * cR), 256>>>(support);
    kreduce<<<1024, 256>>>();
    kout<<<2048, 256>>>(u, v, u_bias, out);
}

// round 13
// speedup vs baseline: 1.7678x; 1.3164x over previous
#include <cuda_runtime.h>
#include <cuda_fp16.h>

typedef unsigned long long ull;
typedef unsigned int u32;

constexpr int cNU = 4096, cNV = 4096, cD = 256, cH = 64, cR = 5, cB = 4096;
constexpr int KSPLIT = 8;
constexpr int KSLICE = 4096 / KSPLIT; // 512
constexpr int NC = KSLICE / 32;       // 16 chunks (BK=32) per block
constexpr int TM = 256;               // block tile rows

// ---------------- device scratch ----------------
__device__ float g_row[cR * cNU];
__device__ float g_col[cR * cNV];
// fp16 image of support (row-major, same layout as S): [r][n][m], 2 fp16 per u32
__device__ u32 g_S16[(size_t)cR * cNU * cNV / 2];
// fp16 hi/lo images of cumsum'd weights * 256: [sid(0..9)][k=256][32 u32 along h]
__device__ u32 g_Wh[10 * 8192];
__device__ u32 g_Wl[10 * 8192];
// fp16 hi/lo images (scale*256 folded): side 0 = tv-side (A_u), side 1 = tu-side (A_v)
__device__ u32 g_Bhi[2 * 5 * 131072];
__device__ u32 g_Blo[2 * 5 * 131072];
__device__ float g_Au[cNU * cH];
__device__ float g_Av[cNV * cH];

// ---------------- helpers ----------------
__device__ __forceinline__ u32 smem_u32(const void* p) {
    u32 a;
    asm("{ .reg .u64 t; cvta.to.shared.u64 t, %1; cvt.u32.u64 %0, t; }" : "=r"(a) : "l"(p));
    return a;
}
__device__ __forceinline__ void split2h(float x0, float x1, u32 &h, u32 &l) {
    __half2 hh = __float22half2_rn(make_float2(x0, x1));
    float2 bk = __half22float2(hh);
    __half2 ll = __float22half2_rn(make_float2(x0 - bk.x, x1 - bk.y));
    h = *(u32*)&hh;
    l = *(u32*)&ll;
}
__device__ __forceinline__ u32 pack2h(float x0, float x1) {
    __half2 hh = __float22half2_rn(make_float2(x0, x1));
    return *(u32*)&hh;
}
__device__ __forceinline__ float invs(float x) {
    return x > 0.f ? rsqrtf(x) : 0.f;
}

#define LDSM4(r, addr) \
    asm volatile("ldmatrix.sync.aligned.m8n8.x4.shared.b16 {%0,%1,%2,%3}, [%4];" \
                 : "=r"((r)[0]), "=r"((r)[1]), "=r"((r)[2]), "=r"((r)[3]) : "r"(addr))
#define LDSM4T(r, addr) \
    asm volatile("ldmatrix.sync.aligned.m8n8.x4.trans.shared.b16 {%0,%1,%2,%3}, [%4];" \
                 : "=r"((r)[0]), "=r"((r)[1]), "=r"((r)[2]), "=r"((r)[3]) : "r"(addr))
#define MMA_F16(c, a, b0, b1) \
    asm volatile("mma.sync.aligned.m16n8k16.row.col.f32.f16.f16.f32 " \
                 "{%0,%1,%2,%3}, {%4,%5,%6,%7}, {%8,%9}, {%0,%1,%2,%3};" \
                 : "+f"((c)[0]), "+f"((c)[1]), "+f"((c)[2]), "+f"((c)[3]) \
                 : "r"((a)[0]), "r"((a)[1]), "r"((a)[2]), "r"((a)[3]), "r"(b0), "r"(b1))
#define CP_ASYNC16(smaddr, gptr) \
    asm volatile("cp.async.ca.shared.global [%0], [%1], 16;" :: "r"(smaddr), "l"(gptr))
#define CP_COMMIT() asm volatile("cp.async.commit_group;" ::: "memory")
#define CP_WAIT0()  asm volatile("cp.async.wait_group 0;" ::: "memory")
#define CP_WAIT1()  asm volatile("cp.async.wait_group 1;" ::: "memory")

// smem swizzles (byte offsets; writer and ldmatrix reader use the same formula)
__device__ __forceinline__ u32 sw_nt(u32 o)  { return o ^ ((o >> 3) & 0x30); } // 64B rows
__device__ __forceinline__ u32 sw_t2(u32 o)  { return o ^ ((o >> 5) & 0x70); } // 512B rows
__device__ __forceinline__ u32 swzA_nt(int row, int k) { return sw_nt((u32)(row * 64 + k * 2)); }
__device__ __forceinline__ u32 swzB(int k, int n) {      // [32][64] fp16, 128B rows
    u32 o = (u32)(k * 128 + n * 2); return o ^ ((o >> 3) & 0x70);
}

// ---------------- tiny kernels ----------------
// zero sum buffers + outputs, cumsum weights + split fp16 hi/lo images (x256)
__global__ void kinit(const float* __restrict__ uw, const float* __restrict__ vw) {
    int i = blockIdx.x * blockDim.x + threadIdx.x;
    if (i < cNU * cH) { g_Au[i] = 0.f; g_Av[i] = 0.f; }
    if (i < cR * cNU) { g_row[i] = 0.f; g_col[i] = 0.f; }
    if (i < cD * cH / 2) {          // 8192 h-pairs
        int k = i >> 5, hp = i & 31;
        float a0 = 0.f, a1 = 0.f, b0 = 0.f, b1 = 0.f;
#pragma unroll
        for (int r = 0; r < cR; r++) {
            a0 += uw[r * cD * cH + k * cH + 2 * hp];
            a1 += uw[r * cD * cH + k * cH + 2 * hp + 1];
            b0 += vw[r * cD * cH + k * cH + 2 * hp];
            b1 += vw[r * cD * cH + k * cH + 2 * hp + 1];
            u32 h, l;
            split2h(256.f * a0, 256.f * a1, h, l);
            g_Wh[(size_t)r * 8192 + k * 32 + hp] = h;
            g_Wl[(size_t)r * 8192 + k * 32 + hp] = l;
            split2h(256.f * b0, 256.f * b1, h, l);
            g_Wh[(size_t)(5 + r) * 8192 + k * 32 + hp] = h;
            g_Wl[(size_t)(5 + r) * 8192 + k * 32 + hp] = l;
        }
    }
}

// row/col sums of support + write fp16 image of S (one pass over S)
__global__ void __launch_bounds__(256) ksums(const float* __restrict__ S) {
    constexpr int RPC = 32;
    int blk = blockIdx.x;
    int r  = blk / (cNU / RPC);
    int n0 = (blk % (cNU / RPC)) * RPC;
    const float* base = S + ((size_t)r * cNU + n0) * cNV;
    int t = threadIdx.x;
    float4 c0 = {0,0,0,0}, c1 = c0, c2 = c0, c3 = c0;
    for (int i = 0; i < RPC; i++) {
        const float4* rp = (const float4*)(base + (size_t)i * cNV);
        float4 v0 = rp[t], v1 = rp[t + 256], v2 = rp[t + 512], v3 = rp[t + 768];
        // fp16 image write (hi of each value; same truncation kmain used before)
        u32* s16 = g_S16 + ((size_t)r * cNU + n0 + i) * (cNV / 2);
        *(uint2*)(s16 + 2 * t)        = make_uint2(pack2h(v0.x, v0.y), pack2h(v0.z, v0.w));
        *(uint2*)(s16 + 2 * t + 512)  = make_uint2(pack2h(v1.x, v1.y), pack2h(v1.z, v1.w));
        *(uint2*)(s16 + 2 * t + 1024) = make_uint2(pack2h(v2.x, v2.y), pack2h(v2.z, v2.w));
        *(uint2*)(s16 + 2 * t + 1536) = make_uint2(pack2h(v3.x, v3.y), pack2h(v3.z, v3.w));
        c0.x += v0.x; c0.y += v0.y; c0.z += v0.z; c0.w += v0.w;
        c1.x += v1.x; c1.y += v1.y; c1.z += v1.z; c1.w += v1.w;
        c2.x += v2.x; c2.y += v2.y; c2.z += v2.z; c2.w += v2.w;
        c3.x += v3.x; c3.y += v3.y; c3.z += v3.z; c3.w += v3.w;
        float rs = v0.x + v0.y + v0.z + v0.w + v1.x + v1.y + v1.z + v1.w
                 + v2.x + v2.y + v2.z + v2.w + v3.x + v3.y + v3.z + v3.w;
#pragma unroll
        for (int o = 16; o > 0; o >>= 1) rs += __shfl_down_sync(0xffffffffu, rs, o);
        if ((t & 31) == 0) atomicAdd(&g_row[r * cNU + n0 + i], rs);
    }
    float* col = g_col + r * cNV;
    int c = 4 * t;
    atomicAdd(&col[c+0],    c0.x); atomicAdd(&col[c+1],    c0.y);
    atomicAdd(&col[c+2],    c0.z); atomicAdd(&col[c+3],    c0.w);
    atomicAdd(&col[c+1024], c1.x); atomicAdd(&col[c+1025], c1.y);
    atomicAdd(&col[c+1026], c1.z); atomicAdd(&col[c+1027], c1.w);
    atomicAdd(&col[c+2048], c2.x); atomicAdd(&col[c+2049], c2.y);
    atomicAdd(&col[c+2050], c2.z); atomicAdd(&col[c+2051], c2.w);
    atomicAdd(&col[c+3072], c3.x); atomicAdd(&col[c+3073], c3.y);
    atomicAdd(&col[c+3074], c3.z); atomicAdd(&col[c+3075], c3.w);
}

// ---------------- feature GEMM on tensor cores (fp16 3-term split) ----------
// tile 128 x 64, K = 256 (8 chunks of BK=32), double buffered.
// smem per buf (24 KB): Fhi @0 (8K), Flo @8192 (8K), Whi @16384 (4K), Wlo @20480 (4K)
__global__ void __launch_bounds__(256, 2) kfeat(const float* __restrict__ u_feat,
                                                const float* __restrict__ v_feat) {
    __shared__ __align__(1024) unsigned char sm[2][24576];
    const int sid = blockIdx.y;
    const bool uside = sid < cR;
    const int r = uside ? sid : sid - cR;
    const float* F = uside ? u_feat : v_feat;
    const u32* Wh = g_Wh + (size_t)sid * 8192;
    const u32* Wl = g_Wl + (size_t)sid * 8192;
    const float* sraw = (uside ? g_row : g_col) + r * 4096;
    const size_t ib = (size_t)(uside ? 5 + r : r) * 131072;
    const int t = threadIdx.x;
    const int wid = t >> 5, lane = t & 31;
    const int mw = (wid & 3) * 32;
    const int nw = (wid >> 2) * 32;
    const int outb = blockIdx.x * 128;
    const u32 sb = smem_u32(sm);

    const int bk_ = t >> 3, bc4 = (t & 7) * 4;
    const u32 offB = swzB(bk_, (t & 7) * 8);

    float acc[8][4];
#pragma unroll
    for (int j = 0; j < 8; j++)
#pragma unroll
        for (int q = 0; q < 4; q++) acc[j][q] = 0.f;

    float4 ra[4];
    auto ldgF = [&](int c) {
        const float4* ap =
            (const float4*)(F + (size_t)(outb + (t >> 1)) * cD + c * 32 + (t & 1) * 16);
        ra[0] = ap[0]; ra[1] = ap[1]; ra[2] = ap[2]; ra[3] = ap[3];
    };
    auto stsF = [&](int b) {
        unsigned char* base = sm[b];
        const float* f = (const float*)ra;
        int row = t >> 1, kk = (t & 1) * 16;
#pragma unroll
        for (int j = 0; j < 8; j++) {
            u32 h, l; split2h(f[2 * j], f[2 * j + 1], h, l);
            u32 off = swzA_nt(row, kk + 2 * j);
            *(u32*)(base + off) = h;
            *(u32*)(base + 8192 + off) = l;
        }
    };
    auto cpW = [&](int c, int b) {
        const u32 sbuf = sb + b * 24576;
        size_t gofs = (size_t)(c * 32 + bk_) * 32 + bc4;
        CP_ASYNC16(sbuf + 16384 + offB, Wh + gofs);
        CP_ASYNC16(sbuf + 20480 + offB, Wl + gofs);
        CP_COMMIT();
    };

    ldgF(0);
    cpW(0, 0);
    stsF(0);
    ldgF(1);

    for (int c = 0; c < 8; c++) {
        CP_WAIT0();
        __syncthreads();
        if (c + 1 < 8) {
            stsF((c + 1) & 1);
            cpW(c + 1, (c + 1) & 1);
            if (c + 2 < 8) ldgF(c + 2);
        }
        const u32 sbuf = sb + (c & 1) * 24576;
#pragma unroll
        for (int s = 0; s < 2; s++) {
            const int k0s = s * 16;
            u32 ah[2][4], al[2][4];
            {
                int arow = mw + (lane & 15);
                int acol = (lane >> 4) * 8 + k0s;
                u32 o0 = swzA_nt(arow, acol), o1 = swzA_nt(arow + 16, acol);
                LDSM4(ah[0], sbuf + o0);
                LDSM4(ah[1], sbuf + o1);
                LDSM4(al[0], sbuf + 8192 + o0);
                LDSM4(al[1], sbuf + 8192 + o1);
            }
            u32 bh[2][4], bl[2][4];
            {
                int krow = k0s + (lane & 15);
#pragma unroll
                for (int g = 0; g < 2; g++) {
                    u32 off = swzB(krow, nw + g * 16 + (lane >> 4) * 8);
                    LDSM4T(bh[g], sbuf + 16384 + off);
                    LDSM4T(bl[g], sbuf + 20480 + off);
                }
            }
#pragma unroll
            for (int mi = 0; mi < 2; mi++)
#pragma unroll
                for (int g = 0; g < 2; g++)
#pragma unroll
                    for (int half = 0; half < 2; half++) {
                        const int j = mi * 4 + g * 2 + half;
                        MMA_F16(acc[j], ah[mi], bh[g][2 * half], bh[g][2 * half + 1]);
                        MMA_F16(acc[j], al[mi], bh[g][2 * half], bh[g][2 * half + 1]);
                        MMA_F16(acc[j], ah[mi], bl[g][2 * half], bl[g][2 * half + 1]);
                    }
        }
    }

    const int g2 = lane >> 2, t2 = lane & 3;
#pragma unroll
    for (int mi = 0; mi < 2; mi++) {
        const int row0 = outb + mw + mi * 16 + g2;
        const int row1 = row0 + 8;
        const float s0 = invs(sraw[row0]);
        const float s1 = invs(sraw[row1]);
#pragma unroll
        for (int ni = 0; ni < 4; ni++) {
            const int j = mi * 4 + ni;
            const int pair = (nw + ni * 8 + 2 * t2) >> 1;
            u32 h, l;
            split2h(s0 * acc[j][0], s0 * acc[j][1], h, l);
            g_Bhi[ib + (size_t)row0 * 32 + pair] = h;
            g_Blo[ib + (size_t)row0 * 32 + pair] = l;
            split2h(s1 * acc[j][2], s1 * acc[j][3], h, l);
            g_Bhi[ib + (size_t)row1 * 32 + pair] = h;
            g_Blo[ib + (size_t)row1 * 32 + pair] = l;
        }
    }
}

// ---------------- main contraction: all-cp.async, 256x64 tile, atomics out ----
// smem per buf (24 KB): A @0 (16K), Bhi @16384 (4K), Blo @20480 (4K)
// warp tile 64(M) x 32(N): warps (wid&3)->M group, (wid>>2)->N group
template <bool TRANS>
__device__ __forceinline__ void kmain_body(unsigned char (*sm)[24576],
                                           int r, int tileb, int ks) {
    const int t = threadIdx.x;
    const int wid = t >> 5, lane = t & 31;
    const int mw = (wid & 3) * 64;
    const int nw = (wid >> 2) * 32;
    const float* sraw = (TRANS ? g_col : g_row) + r * 4096;
    const int sr = (TRANS ? 5 : 0) + r;
    const u32* imgh = g_Bhi + (size_t)sr * 131072;
    const u32* imgl = g_Blo + (size_t)sr * 131072;
    const char* S16r = (const char*)(g_S16 + (size_t)r * cNU * (cNV / 2));
    const int kbase = ks * KSLICE;
    const u32 sb = smem_u32(sm);

    const int bk_ = t >> 3, bc4 = (t & 7) * 4;
    const u32 offB = swzB(bk_, (t & 7) * 8);

    float acc[16][4];
#pragma unroll
    for (int j = 0; j < 16; j++)
#pragma unroll
        for (int q = 0; q < 4; q++) acc[j][q] = 0.f;

    auto cpAB = [&](int c, int b) {
        const u32 sbuf = sb + b * 24576;
        const int kk0 = kbase + c * 32;
        if (!TRANS) {
            // A tile: 256 rows x 32 k fp16 (64B/row)
#pragma unroll
            for (int q = 0; q < 4; q++) {
                int idx = t + q * 256;
                int row = idx >> 2, c16 = idx & 3;
                CP_ASYNC16(sbuf + sw_nt((u32)(row * 64 + c16 * 16)),
                           S16r + (size_t)(tileb + row) * 8192 + kk0 * 2 + c16 * 16);
            }
        } else {
            // A^T tile: 32 k-rows x 256 cols fp16 (512B/row)
#pragma unroll
            for (int q = 0; q < 4; q++) {
                int idx = t + q * 256;
                int krow = idx >> 5, c16 = idx & 31;
                CP_ASYNC16(sbuf + sw_t2((u32)(krow * 512 + c16 * 16)),
                           S16r + (size_t)(kk0 + krow) * 8192 + tileb * 2 + c16 * 16);
            }
        }
        size_t gofs = (size_t)(kk0 + bk_) * 32 + bc4;
        CP_ASYNC16(sbuf + 16384 + offB, imgh + gofs);
        CP_ASYNC16(sbuf + 20480 + offB, imgl + gofs);
        CP_COMMIT();
    };

    cpAB(0, 0);
    for (int c = 0; c < NC; c++) {
        if (c + 1 < NC) { cpAB(c + 1, (c + 1) & 1); CP_WAIT1(); }
        else            { CP_WAIT0(); }
        __syncthreads();
        const u32 sbuf = sb + (c & 1) * 24576;
#pragma unroll
        for (int s = 0; s < 2; s++) {
            const int k0s = s * 16;
            u32 a[4][4];
            if (!TRANS) {
                int arow = mw + (lane & 15);
                int acol = (lane >> 4) * 8 + k0s;
#pragma unroll
                for (int mi = 0; mi < 4; mi++)
                    LDSM4(a[mi], sbuf + sw_nt((u32)((arow + 16 * mi) * 64 + acol * 2)));
            } else {
                int krow = k0s + (lane & 7) + ((lane >> 4) << 3);
                int col0 = mw + ((lane >> 3) & 1) * 8;
#pragma unroll
                for (int mi = 0; mi < 4; mi++)
                    LDSM4T(a[mi], sbuf + sw_t2((u32)(krow * 512 + (col0 + 16 * mi) * 2)));
            }
            u32 bh[2][4], bl[2][4];
            {
                int krow = k0s + (lane & 15);
#pragma unroll
                for (int g = 0; g < 2; g++) {
                    u32 off = swzB(krow, nw + g * 16 + (lane >> 4) * 8);
                    LDSM4T(bh[g], sbuf + 16384 + off);
                    LDSM4T(bl[g], sbuf + 20480 + off);
                }
            }
#pragma unroll
            for (int mi = 0; mi < 4; mi++)
#pragma unroll
                for (int g = 0; g < 2; g++)
#pragma unroll
                    for (int half = 0; half < 2; half++) {
                        const int j = mi * 4 + g * 2 + half;
                        MMA_F16(acc[j], a[mi], bh[g][2 * half], bh[g][2 * half + 1]);
                        MMA_F16(acc[j], a[mi], bl[g][2 * half], bl[g][2 * half + 1]);
                    }
        }
        __syncthreads();
    }

    // epilogue: scale + atomic accumulate into final output matrix
    const int g2 = lane >> 2, t2 = lane & 3;
    float* Aout = TRANS ? g_Av : g_Au;
#pragma unroll
    for (int mi = 0; mi < 4; mi++) {
        const int row0 = tileb + mw + mi * 16 + g2;
        const int row1 = row0 + 8;
        const float s0 = invs(sraw[row0]) * 0.00390625f;  // undo 256x image pre-scale
        const float s1 = invs(sraw[row1]) * 0.00390625f;
#pragma unroll
        for (int ni = 0; ni < 4; ni++) {
            const int j = mi * 4 + ni;
            const int col = nw + ni * 8 + 2 * t2;
            atomicAdd(&Aout[(size_t)row0 * 64 + col],     s0 * acc[j][0]);
            atomicAdd(&Aout[(size_t)row0 * 64 + col + 1], s0 * acc[j][1]);
            atomicAdd(&Aout[(size_t)row1 * 64 + col],     s1 * acc[j][2]);
            atomicAdd(&Aout[(size_t)row1 * 64 + col + 1], s1 * acc[j][3]);
        }
    }
}

__global__ void __launch_bounds__(256, 2) kmain_all() {
    __shared__ __align__(1024) unsigned char sm[2][24576];
    const int z = blockIdx.z;
    const int side = z / cR, r = z % cR;
    const int tileb = blockIdx.x * TM;
    const int ks = blockIdx.y;
    if (side == 0) kmain_body<false>(sm, r, tileb, ks);
    else           kmain_body<true >(sm, r, tileb, ks);
}

__global__ void kout(const int* __restrict__ u, const int* __restrict__ v,
                     const float* __restrict__ bias, float* __restrict__ out) {
    int i = blockIdx.x * blockDim.x + threadIdx.x;
    if (i >= 2 * cB * cH) return;
    int h = i & 63;
    float bv = bias[h];
    float z;
    if (i < cB * cH) {
        int b = i >> 6;
        z = g_Au[(size_t)u[b] * cH + h] + bv;
    } else {
        int b = (i - cB * cH) >> 6;
        z = g_Av[(size_t)v[b] * cH + h] + bv;
    }
    out[i] = z > 0.f ? z : 0.f;
}

// ---------------- launch ----------------
extern "C" void kernel_launch(void* const* d_in, const int* in_sizes, int n_in,
                              void* d_out, int out_size) {
    const float* u_feat   = (const float*)d_in[0];
    const float* v_feat   = (const float*)d_in[1];
    const int*   u        = (const int*)d_in[2];
    const int*   v        = (const int*)d_in[3];
    const float* support  = (const float*)d_in[4];
    const float* u_weight = (const float*)d_in[5];
    const float* v_weight = (const float*)d_in[6];
    const float* u_bias   = (const float*)d_in[7];
    float* out = (float*)d_out;

    kinit<<<1024, 256>>>(u_weight, v_weight);
    ksums<<<640, 256>>>(support);
    kfeat<<<dim3(32, 10), 256>>>(u_feat, v_feat);
    kmain_all<<<dim3(cNU / TM, KSPLIT, 2 * cR), 256>>>();
    kout<<<2048, 256>>>(u, v, u_bias, out);
}

// round 14
// speedup vs baseline: 2.0729x; 1.1726x over previous
#include <cuda_runtime.h>
#include <cuda_fp16.h>

typedef unsigned long long ull;
typedef unsigned int u32;

constexpr int cNU = 4096, cNV = 4096, cD = 256, cH = 64, cR = 5, cB = 4096;
constexpr int KSPLIT = 8;
constexpr int KSLICE = 4096 / KSPLIT; // 512
constexpr int NC = KSLICE / 32;       // 16 chunks (BK=32) per block
constexpr int TM = 256;               // block tile rows

// ---------------- device scratch ----------------
__device__ float g_row[cR * cNU];
__device__ float g_col[cR * cNV];
// fp16 image of support (row-major, same layout as S): [r][n][m], 2 fp16 per u32
__device__ u32 g_S16[(size_t)cR * cNU * cNV / 2];
// fp16 hi/lo images of cumsum'd weights * 256: [sid(0..9)][k=256][32 u32 along h]
__device__ u32 g_Wh[10 * 8192];
__device__ u32 g_Wl[10 * 8192];
// fp16 image (scale*256 folded): side 0 = tv-side (A_u), side 1 = tu-side (A_v)
__device__ u32 g_Bhi[2 * 5 * 131072];
__device__ float g_Au[cNU * cH];
__device__ float g_Av[cNV * cH];

// ---------------- helpers ----------------
__device__ __forceinline__ u32 smem_u32(const void* p) {
    u32 a;
    asm("{ .reg .u64 t; cvta.to.shared.u64 t, %1; cvt.u32.u64 %0, t; }" : "=r"(a) : "l"(p));
    return a;
}
__device__ __forceinline__ void split2h(float x0, float x1, u32 &h, u32 &l) {
    __half2 hh = __float22half2_rn(make_float2(x0, x1));
    float2 bk = __half22float2(hh);
    __half2 ll = __float22half2_rn(make_float2(x0 - bk.x, x1 - bk.y));
    h = *(u32*)&hh;
    l = *(u32*)&ll;
}
__device__ __forceinline__ u32 pack2h(float x0, float x1) {
    __half2 hh = __float22half2_rn(make_float2(x0, x1));
    return *(u32*)&hh;
}
__device__ __forceinline__ float invs(float x) {
    return x > 0.f ? rsqrtf(x) : 0.f;
}

#define LDSM4(r, addr) \
    asm volatile("ldmatrix.sync.aligned.m8n8.x4.shared.b16 {%0,%1,%2,%3}, [%4];" \
                 : "=r"((r)[0]), "=r"((r)[1]), "=r"((r)[2]), "=r"((r)[3]) : "r"(addr))
#define LDSM4T(r, addr) \
    asm volatile("ldmatrix.sync.aligned.m8n8.x4.trans.shared.b16 {%0,%1,%2,%3}, [%4];" \
                 : "=r"((r)[0]), "=r"((r)[1]), "=r"((r)[2]), "=r"((r)[3]) : "r"(addr))
#define MMA_F16(c, a, b0, b1) \
    asm volatile("mma.sync.aligned.m16n8k16.row.col.f32.f16.f16.f32 " \
                 "{%0,%1,%2,%3}, {%4,%5,%6,%7}, {%8,%9}, {%0,%1,%2,%3};" \
                 : "+f"((c)[0]), "+f"((c)[1]), "+f"((c)[2]), "+f"((c)[3]) \
                 : "r"((a)[0]), "r"((a)[1]), "r"((a)[2]), "r"((a)[3]), "r"(b0), "r"(b1))
#define CP_ASYNC16(smaddr, gptr) \
    asm volatile("cp.async.ca.shared.global [%0], [%1], 16;" :: "r"(smaddr), "l"(gptr))
#define CP_COMMIT() asm volatile("cp.async.commit_group;" ::: "memory")
#define CP_WAIT0()  asm volatile("cp.async.wait_group 0;" ::: "memory")
#define CP_WAIT1()  asm volatile("cp.async.wait_group 1;" ::: "memory")

// smem swizzles (byte offsets; writer and ldmatrix reader use the same formula)
__device__ __forceinline__ u32 sw_nt(u32 o)  { return o ^ ((o >> 3) & 0x30); } // 64B rows
__device__ __forceinline__ u32 sw_t2(u32 o)  { return o ^ ((o >> 5) & 0x70); } // 512B rows
__device__ __forceinline__ u32 swzA_nt(int row, int k) { return sw_nt((u32)(row * 64 + k * 2)); }
__device__ __forceinline__ u32 swzB(int k, int n) {      // [32][64] fp16, 128B rows
    u32 o = (u32)(k * 128 + n * 2); return o ^ ((o >> 3) & 0x70);
}

// ---------------- tiny kernels ----------------
__global__ void kinit(const float* __restrict__ uw, const float* __restrict__ vw) {
    int i = blockIdx.x * blockDim.x + threadIdx.x;
    if (i < cNU * cH) { g_Au[i] = 0.f; g_Av[i] = 0.f; }
    if (i < cR * cNU) { g_row[i] = 0.f; g_col[i] = 0.f; }
    if (i < cD * cH / 2) {          // 8192 h-pairs
        int k = i >> 5, hp = i & 31;
        float a0 = 0.f, a1 = 0.f, b0 = 0.f, b1 = 0.f;
#pragma unroll
        for (int r = 0; r < cR; r++) {
            a0 += uw[r * cD * cH + k * cH + 2 * hp];
            a1 += uw[r * cD * cH + k * cH + 2 * hp + 1];
            b0 += vw[r * cD * cH + k * cH + 2 * hp];
            b1 += vw[r * cD * cH + k * cH + 2 * hp + 1];
            u32 h, l;
            split2h(256.f * a0, 256.f * a1, h, l);
            g_Wh[(size_t)r * 8192 + k * 32 + hp] = h;
            g_Wl[(size_t)r * 8192 + k * 32 + hp] = l;
            split2h(256.f * b0, 256.f * b1, h, l);
            g_Wh[(size_t)(5 + r) * 8192 + k * 32 + hp] = h;
            g_Wl[(size_t)(5 + r) * 8192 + k * 32 + hp] = l;
        }
    }
}

// row/col sums of support + write fp16 image of S (one pass over S)
__global__ void __launch_bounds__(256) ksums(const float* __restrict__ S) {
    constexpr int RPC = 32;
    int blk = blockIdx.x;
    int r  = blk / (cNU / RPC);
    int n0 = (blk % (cNU / RPC)) * RPC;
    const float* base = S + ((size_t)r * cNU + n0) * cNV;
    int t = threadIdx.x;
    float4 c0 = {0,0,0,0}, c1 = c0, c2 = c0, c3 = c0;
    for (int i = 0; i < RPC; i++) {
        const float4* rp = (const float4*)(base + (size_t)i * cNV);
        float4 v0 = rp[t], v1 = rp[t + 256], v2 = rp[t + 512], v3 = rp[t + 768];
        u32* s16 = g_S16 + ((size_t)r * cNU + n0 + i) * (cNV / 2);
        *(uint2*)(s16 + 2 * t)        = make_uint2(pack2h(v0.x, v0.y), pack2h(v0.z, v0.w));
        *(uint2*)(s16 + 2 * t + 512)  = make_uint2(pack2h(v1.x, v1.y), pack2h(v1.z, v1.w));
        *(uint2*)(s16 + 2 * t + 1024) = make_uint2(pack2h(v2.x, v2.y), pack2h(v2.z, v2.w));
        *(uint2*)(s16 + 2 * t + 1536) = make_uint2(pack2h(v3.x, v3.y), pack2h(v3.z, v3.w));
        c0.x += v0.x; c0.y += v0.y; c0.z += v0.z; c0.w += v0.w;
        c1.x += v1.x; c1.y += v1.y; c1.z += v1.z; c1.w += v1.w;
        c2.x += v2.x; c2.y += v2.y; c2.z += v2.z; c2.w += v2.w;
        c3.x += v3.x; c3.y += v3.y; c3.z += v3.z; c3.w += v3.w;
        float rs = v0.x + v0.y + v0.z + v0.w + v1.x + v1.y + v1.z + v1.w
                 + v2.x + v2.y + v2.z + v2.w + v3.x + v3.y + v3.z + v3.w;
#pragma unroll
        for (int o = 16; o > 0; o >>= 1) rs += __shfl_down_sync(0xffffffffu, rs, o);
        if ((t & 31) == 0) atomicAdd(&g_row[r * cNU + n0 + i], rs);
    }
    float* col = g_col + r * cNV;
    int c = 4 * t;
    atomicAdd(&col[c+0],    c0.x); atomicAdd(&col[c+1],    c0.y);
    atomicAdd(&col[c+2],    c0.z); atomicAdd(&col[c+3],    c0.w);
    atomicAdd(&col[c+1024], c1.x); atomicAdd(&col[c+1025], c1.y);
    atomicAdd(&col[c+1026], c1.z); atomicAdd(&col[c+1027], c1.w);
    atomicAdd(&col[c+2048], c2.x); atomicAdd(&col[c+2049], c2.y);
    atomicAdd(&col[c+2050], c2.z); atomicAdd(&col[c+2051], c2.w);
    atomicAdd(&col[c+3072], c3.x); atomicAdd(&col[c+3073], c3.y);
    atomicAdd(&col[c+3074], c3.z); atomicAdd(&col[c+3075], c3.w);
}

// ---------------- feature GEMM on tensor cores (fp16 3-term split) ----------
// tile 128 x 64, K = 256 (8 chunks of BK=32), double buffered.
// smem per buf (24 KB): Fhi @0 (8K), Flo @8192 (8K), Whi @16384 (4K), Wlo @20480 (4K)
__global__ void __launch_bounds__(256, 2) kfeat(const float* __restrict__ u_feat,
                                                const float* __restrict__ v_feat) {
    __shared__ __align__(1024) unsigned char sm[2][24576];
    const int sid = blockIdx.y;
    const bool uside = sid < cR;
    const int r = uside ? sid : sid - cR;
    const float* F = uside ? u_feat : v_feat;
    const u32* Wh = g_Wh + (size_t)sid * 8192;
    const u32* Wl = g_Wl + (size_t)sid * 8192;
    const float* sraw = (uside ? g_row : g_col) + r * 4096;
    const size_t ib = (size_t)(uside ? 5 + r : r) * 131072;
    const int t = threadIdx.x;
    const int wid = t >> 5, lane = t & 31;
    const int mw = (wid & 3) * 32;
    const int nw = (wid >> 2) * 32;
    const int outb = blockIdx.x * 128;
    const u32 sb = smem_u32(sm);

    const int bk_ = t >> 3, bc4 = (t & 7) * 4;
    const u32 offB = swzB(bk_, (t & 7) * 8);

    float acc[8][4];
#pragma unroll
    for (int j = 0; j < 8; j++)
#pragma unroll
        for (int q = 0; q < 4; q++) acc[j][q] = 0.f;

    float4 ra[4];
    auto ldgF = [&](int c) {
        const float4* ap =
            (const float4*)(F + (size_t)(outb + (t >> 1)) * cD + c * 32 + (t & 1) * 16);
        ra[0] = ap[0]; ra[1] = ap[1]; ra[2] = ap[2]; ra[3] = ap[3];
    };
    auto stsF = [&](int b) {
        unsigned char* base = sm[b];
        const float* f = (const float*)ra;
        int row = t >> 1, kk = (t & 1) * 16;
#pragma unroll
        for (int j = 0; j < 8; j++) {
            u32 h, l; split2h(f[2 * j], f[2 * j + 1], h, l);
            u32 off = swzA_nt(row, kk + 2 * j);
            *(u32*)(base + off) = h;
            *(u32*)(base + 8192 + off) = l;
        }
    };
    auto cpW = [&](int c, int b) {
        const u32 sbuf = sb + b * 24576;
        size_t gofs = (size_t)(c * 32 + bk_) * 32 + bc4;
        CP_ASYNC16(sbuf + 16384 + offB, Wh + gofs);
        CP_ASYNC16(sbuf + 20480 + offB, Wl + gofs);
        CP_COMMIT();
    };

    ldgF(0);
    cpW(0, 0);
    stsF(0);
    ldgF(1);

    for (int c = 0; c < 8; c++) {
        CP_WAIT0();
        __syncthreads();
        if (c + 1 < 8) {
            stsF((c + 1) & 1);
            cpW(c + 1, (c + 1) & 1);
            if (c + 2 < 8) ldgF(c + 2);
        }
        const u32 sbuf = sb + (c & 1) * 24576;
#pragma unroll
        for (int s = 0; s < 2; s++) {
            const int k0s = s * 16;
            u32 ah[2][4], al[2][4];
            {
                int arow = mw + (lane & 15);
                int acol = (lane >> 4) * 8 + k0s;
                u32 o0 = swzA_nt(arow, acol), o1 = swzA_nt(arow + 16, acol);
                LDSM4(ah[0], sbuf + o0);
                LDSM4(ah[1], sbuf + o1);
                LDSM4(al[0], sbuf + 8192 + o0);
                LDSM4(al[1], sbuf + 8192 + o1);
            }
            u32 bh[2][4], bl[2][4];
            {
                int krow = k0s + (lane & 15);
#pragma unroll
                for (int g = 0; g < 2; g++) {
                    u32 off = swzB(krow, nw + g * 16 + (lane >> 4) * 8);
                    LDSM4T(bh[g], sbuf + 16384 + off);
                    LDSM4T(bl[g], sbuf + 20480 + off);
                }
            }
#pragma unroll
            for (int mi = 0; mi < 2; mi++)
#pragma unroll
                for (int g = 0; g < 2; g++)
#pragma unroll
                    for (int half = 0; half < 2; half++) {
                        const int j = mi * 4 + g * 2 + half;
                        MMA_F16(acc[j], ah[mi], bh[g][2 * half], bh[g][2 * half + 1]);
                        MMA_F16(acc[j], al[mi], bh[g][2 * half], bh[g][2 * half + 1]);
                        MMA_F16(acc[j], ah[mi], bl[g][2 * half], bl[g][2 * half + 1]);
                    }
        }
    }

    // epilogue: scale by rsqrt(sum), pack fp16 hi image only
    const int g2 = lane >> 2, t2 = lane & 3;
#pragma unroll
    for (int mi = 0; mi < 2; mi++) {
        const int row0 = outb + mw + mi * 16 + g2;
        const int row1 = row0 + 8;
        const float s0 = invs(sraw[row0]);
        const float s1 = invs(sraw[row1]);
#pragma unroll
        for (int ni = 0; ni < 4; ni++) {
            const int j = mi * 4 + ni;
            const int pair = (nw + ni * 8 + 2 * t2) >> 1;
            g_Bhi[ib + (size_t)row0 * 32 + pair] = pack2h(s0 * acc[j][0], s0 * acc[j][1]);
            g_Bhi[ib + (size_t)row1 * 32 + pair] = pack2h(s1 * acc[j][2], s1 * acc[j][3]);
        }
    }
}

// ---------------- main contraction: single-fp16, 3-stage pipeline ----------
// smem per stage (20 KB): A @0 (16K), B @16384 (4K); 3 stages = 60 KB
template <bool TRANS>
__device__ __forceinline__ void kmain_body(unsigned char (*sm)[20480],
                                           int r, int tileb, int ks) {
    const int t = threadIdx.x;
    const int wid = t >> 5, lane = t & 31;
    const int mw = (wid & 3) * 64;
    const int nw = (wid >> 2) * 32;
    const float* sraw = (TRANS ? g_col : g_row) + r * 4096;
    const int sr = (TRANS ? 5 : 0) + r;
    const u32* imgh = g_Bhi + (size_t)sr * 131072;
    const char* S16r = (const char*)(g_S16 + (size_t)r * cNU * (cNV / 2));
    const int kbase = ks * KSLICE;
    const u32 sb = smem_u32(sm);

    const int bk_ = t >> 3, bc4 = (t & 7) * 4;
    const u32 offB = swzB(bk_, (t & 7) * 8);

    float acc[16][4];
#pragma unroll
    for (int j = 0; j < 16; j++)
#pragma unroll
        for (int q = 0; q < 4; q++) acc[j][q] = 0.f;

    auto cpAB = [&](int c, int b) {
        const u32 sbuf = sb + b * 20480;
        const int kk0 = kbase + c * 32;
        if (!TRANS) {
#pragma unroll
            for (int q = 0; q < 4; q++) {
                int idx = t + q * 256;
                int row = idx >> 2, c16 = idx & 3;
                CP_ASYNC16(sbuf + sw_nt((u32)(row * 64 + c16 * 16)),
                           S16r + (size_t)(tileb + row) * 8192 + kk0 * 2 + c16 * 16);
            }
        } else {
#pragma unroll
            for (int q = 0; q < 4; q++) {
                int idx = t + q * 256;
                int krow = idx >> 5, c16 = idx & 31;
                CP_ASYNC16(sbuf + sw_t2((u32)(krow * 512 + c16 * 16)),
                           S16r + (size_t)(kk0 + krow) * 8192 + tileb * 2 + c16 * 16);
            }
        }
        CP_ASYNC16(sbuf + 16384 + offB, imgh + (size_t)(kk0 + bk_) * 32 + bc4);
        CP_COMMIT();
    };

    cpAB(0, 0);
    cpAB(1, 1);
    for (int c = 0; c < NC; c++) {
        if (c + 2 < NC) { CP_WAIT1(); }
        else            { CP_WAIT0(); }
        __syncthreads();
        const u32 sbuf = sb + (c % 3) * 20480;
#pragma unroll
        for (int s = 0; s < 2; s++) {
            const int k0s = s * 16;
            u32 a[4][4];
            if (!TRANS) {
                int arow = mw + (lane & 15);
                int acol = (lane >> 4) * 8 + k0s;
#pragma unroll
                for (int mi = 0; mi < 4; mi++)
                    LDSM4(a[mi], sbuf + sw_nt((u32)((arow + 16 * mi) * 64 + acol * 2)));
            } else {
                int krow = k0s + (lane & 7) + ((lane >> 4) << 3);
                int col0 = mw + ((lane >> 3) & 1) * 8;
#pragma unroll
                for (int mi = 0; mi < 4; mi++)
                    LDSM4T(a[mi], sbuf + sw_t2((u32)(krow * 512 + (col0 + 16 * mi) * 2)));
            }
            u32 bh[2][4];
            {
                int krow = k0s + (lane & 15);
#pragma unroll
                for (int g = 0; g < 2; g++)
                    LDSM4T(bh[g], sbuf + 16384 + swzB(krow, nw + g * 16 + (lane >> 4) * 8));
            }
#pragma unroll
            for (int mi = 0; mi < 4; mi++)
#pragma unroll
                for (int g = 0; g < 2; g++)
#pragma unroll
                    for (int half = 0; half < 2; half++) {
                        const int j = mi * 4 + g * 2 + half;
                        MMA_F16(acc[j], a[mi], bh[g][2 * half], bh[g][2 * half + 1]);
                    }
        }
        __syncthreads();
        if (c + 2 < NC) cpAB(c + 2, (c + 2) % 3);
    }

    // epilogue: scale + atomic accumulate into final output matrix
    const int g2 = lane >> 2, t2 = lane & 3;
    float* Aout = TRANS ? g_Av : g_Au;
#pragma unroll
    for (int mi = 0; mi < 4; mi++) {
        const int row0 = tileb + mw + mi * 16 + g2;
        const int row1 = row0 + 8;
        const float s0 = invs(sraw[row0]) * 0.00390625f;  // undo 256x image pre-scale
        const float s1 = invs(sraw[row1]) * 0.00390625f;
#pragma unroll
        for (int ni = 0; ni < 4; ni++) {
            const int j = mi * 4 + ni;
            const int col = nw + ni * 8 + 2 * t2;
            atomicAdd(&Aout[(size_t)row0 * 64 + col],     s0 * acc[j][0]);
            atomicAdd(&Aout[(size_t)row0 * 64 + col + 1], s0 * acc[j][1]);
            atomicAdd(&Aout[(size_t)row1 * 64 + col],     s1 * acc[j][2]);
            atomicAdd(&Aout[(size_t)row1 * 64 + col + 1], s1 * acc[j][3]);
        }
    }
}

__global__ void __launch_bounds__(256, 2) kmain_all() {
    __shared__ __align__(1024) unsigned char sm[3][20480];
    const int z = blockIdx.z;
    const int side = z / cR, r = z % cR;
    const int tileb = blockIdx.x * TM;
    const int ks = blockIdx.y;
    if (side == 0) kmain_body<false>(sm, r, tileb, ks);
    else           kmain_body<true >(sm, r, tileb, ks);
}

__global__ void kout(const int* __restrict__ u, const int* __restrict__ v,
                     const float* __restrict__ bias, float* __restrict__ out) {
    int i = blockIdx.x * blockDim.x + threadIdx.x;
    if (i >= 2 * cB * cH) return;
    int h = i & 63;
    float bv = bias[h];
    float z;
    if (i < cB * cH) {
        int b = i >> 6;
        z = g_Au[(size_t)u[b] * cH + h] + bv;
    } else {
        int b = (i - cB * cH) >> 6;
        z = g_Av[(size_t)v[b] * cH + h] + bv;
    }
    out[i] = z > 0.f ? z : 0.f;
}

// ---------------- launch ----------------
extern "C" void kernel_launch(void* const* d_in, const int* in_sizes, int n_in,
                              void* d_out, int out_size) {
    const float* u_feat   = (const float*)d_in[0];
    const float* v_feat   = (const float*)d_in[1];
    const int*   u        = (const int*)d_in[2];
    const int*   v        = (const int*)d_in[3];
    const float* support  = (const float*)d_in[4];
    const float* u_weight = (const float*)d_in[5];
    const float* v_weight = (const float*)d_in[6];
    const float* u_bias   = (const float*)d_in[7];
    float* out = (float*)d_out;

    kinit<<<1024, 256>>>(u_weight, v_weight);
    ksums<<<640, 256>>>(support);
    kfeat<<<dim3(32, 10), 256>>>(u_feat, v_feat);
    kmain_all<<<dim3(cNU / TM, KSPLIT, 2 * cR), 256>>>();
    kout<<<2048, 256>>>(u, v, u_bias, out);
}

// round 16
// speedup vs baseline: 2.1362x; 1.0305x over previous
#include <cuda_runtime.h>
#include <cuda_fp16.h>

typedef unsigned long long ull;
typedef unsigned int u32;

constexpr int cNU = 4096, cNV = 4096, cD = 256, cH = 64, cR = 5, cB = 4096;
constexpr int KSPLIT = 4;
constexpr int KSLICE = 4096 / KSPLIT; // 1024
constexpr int NC = KSLICE / 32;       // 32 chunks (BK=32) per block
constexpr int TM = 256;               // block tile rows

// ---------------- device scratch ----------------
__device__ float g_row[cR * cNU];
__device__ float g_col[cR * cNV];
// fp16 image of support (row-major, same layout as S): [r][n][m], 2 fp16 per u32
__device__ u32 g_S16[(size_t)cR * cNU * cNV / 2];
// fp16 hi/lo images of cumsum'd weights * 256: [sid(0..9)][k=256][32 u32 along h]
__device__ u32 g_Wh[10 * 8192];
__device__ u32 g_Wl[10 * 8192];
// fp16 image (scale*256 folded): side 0 = tv-side (A_u), side 1 = tu-side (A_v)
__device__ u32 g_Bhi[2 * 5 * 131072];
__device__ float g_Au[cNU * cH];
__device__ float g_Av[cNV * cH];

// ---------------- helpers ----------------
__device__ __forceinline__ u32 smem_u32(const void* p) {
    u32 a;
    asm("{ .reg .u64 t; cvta.to.shared.u64 t, %1; cvt.u32.u64 %0, t; }" : "=r"(a) : "l"(p));
    return a;
}
__device__ __forceinline__ void split2h(float x0, float x1, u32 &h, u32 &l) {
    __half2 hh = __float22half2_rn(make_float2(x0, x1));
    float2 bk = __half22float2(hh);
    __half2 ll = __float22half2_rn(make_float2(x0 - bk.x, x1 - bk.y));
    h = *(u32*)&hh;
    l = *(u32*)&ll;
}
__device__ __forceinline__ u32 pack2h(float x0, float x1) {
    __half2 hh = __float22half2_rn(make_float2(x0, x1));
    return *(u32*)&hh;
}
__device__ __forceinline__ float invs(float x) {
    return x > 0.f ? rsqrtf(x) : 0.f;
}

#define LDSM4(r, addr) \
    asm volatile("ldmatrix.sync.aligned.m8n8.x4.shared.b16 {%0,%1,%2,%3}, [%4];" \
                 : "=r"((r)[0]), "=r"((r)[1]), "=r"((r)[2]), "=r"((r)[3]) : "r"(addr))
#define LDSM4T(r, addr) \
    asm volatile("ldmatrix.sync.aligned.m8n8.x4.trans.shared.b16 {%0,%1,%2,%3}, [%4];" \
                 : "=r"((r)[0]), "=r"((r)[1]), "=r"((r)[2]), "=r"((r)[3]) : "r"(addr))
#define MMA_F16(c, a, b0, b1) \
    asm volatile("mma.sync.aligned.m16n8k16.row.col.f32.f16.f16.f32 " \
                 "{%0,%1,%2,%3}, {%4,%5,%6,%7}, {%8,%9}, {%0,%1,%2,%3};" \
                 : "+f"((c)[0]), "+f"((c)[1]), "+f"((c)[2]), "+f"((c)[3]) \
                 : "r"((a)[0]), "r"((a)[1]), "r"((a)[2]), "r"((a)[3]), "r"(b0), "r"(b1))
#define CP_ASYNC16(smaddr, gptr) \
    asm volatile("cp.async.ca.shared.global [%0], [%1], 16;" :: "r"(smaddr), "l"(gptr))
#define CP_COMMIT() asm volatile("cp.async.commit_group;" ::: "memory")
#define CP_WAIT0()  asm volatile("cp.async.wait_group 0;" ::: "memory")
#define CP_WAIT1()  asm volatile("cp.async.wait_group 1;" ::: "memory")
#define CP_WAIT2()  asm volatile("cp.async.wait_group 2;" ::: "memory")
#define REDV2(addr, x, y) \
    asm volatile("red.global.add.v2.f32 [%0], {%1, %2};" :: "l"(addr), "f"(x), "f"(y) : "memory")

// smem swizzles (byte offsets; writer and ldmatrix reader use the same formula)
__device__ __forceinline__ u32 sw_nt(u32 o)  { return o ^ ((o >> 3) & 0x30); } // 64B rows
__device__ __forceinline__ u32 sw_t2(u32 o)  { return o ^ ((o >> 5) & 0x70); } // 512B rows
__device__ __forceinline__ u32 swzA_nt(int row, int k) { return sw_nt((u32)(row * 64 + k * 2)); }
__device__ __forceinline__ u32 swzB(int k, int n) {      // [32][64] fp16, 128B rows
    u32 o = (u32)(k * 128 + n * 2); return o ^ ((o >> 3) & 0x70);
}

// ---------------- tiny kernels ----------------
__global__ void kinit(const float* __restrict__ uw, const float* __restrict__ vw) {
    int i = blockIdx.x * blockDim.x + threadIdx.x;
    if (i < cNU * cH) { g_Au[i] = 0.f; g_Av[i] = 0.f; }
    if (i < cR * cNU) { g_row[i] = 0.f; g_col[i] = 0.f; }
    if (i < cD * cH / 2) {          // 8192 h-pairs
        int k = i >> 5, hp = i & 31;
        float a0 = 0.f, a1 = 0.f, b0 = 0.f, b1 = 0.f;
#pragma unroll
        for (int r = 0; r < cR; r++) {
            a0 += uw[r * cD * cH + k * cH + 2 * hp];
            a1 += uw[r * cD * cH + k * cH + 2 * hp + 1];
            b0 += vw[r * cD * cH + k * cH + 2 * hp];
            b1 += vw[r * cD * cH + k * cH + 2 * hp + 1];
            u32 h, l;
            split2h(256.f * a0, 256.f * a1, h, l);
            g_Wh[(size_t)r * 8192 + k * 32 + hp] = h;
            g_Wl[(size_t)r * 8192 + k * 32 + hp] = l;
            split2h(256.f * b0, 256.f * b1, h, l);
            g_Wh[(size_t)(5 + r) * 8192 + k * 32 + hp] = h;
            g_Wl[(size_t)(5 + r) * 8192 + k * 32 + hp] = l;
        }
    }
}

// row/col sums of support + write fp16 image of S (one pass over S)
__global__ void __launch_bounds__(256) ksums(const float* __restrict__ S) {
    constexpr int RPC = 32;
    int blk = blockIdx.x;
    int r  = blk / (cNU / RPC);
    int n0 = (blk % (cNU / RPC)) * RPC;
    const float* base = S + ((size_t)r * cNU + n0) * cNV;
    int t = threadIdx.x;
    float4 c0 = {0,0,0,0}, c1 = c0, c2 = c0, c3 = c0;
    for (int i = 0; i < RPC; i++) {
        const float4* rp = (const float4*)(base + (size_t)i * cNV);
        float4 v0 = rp[t], v1 = rp[t + 256], v2 = rp[t + 512], v3 = rp[t + 768];
        u32* s16 = g_S16 + ((size_t)r * cNU + n0 + i) * (cNV / 2);
        *(uint2*)(s16 + 2 * t)        = make_uint2(pack2h(v0.x, v0.y), pack2h(v0.z, v0.w));
        *(uint2*)(s16 + 2 * t + 512)  = make_uint2(pack2h(v1.x, v1.y), pack2h(v1.z, v1.w));
        *(uint2*)(s16 + 2 * t + 1024) = make_uint2(pack2h(v2.x, v2.y), pack2h(v2.z, v2.w));
        *(uint2*)(s16 + 2 * t + 1536) = make_uint2(pack2h(v3.x, v3.y), pack2h(v3.z, v3.w));
        c0.x += v0.x; c0.y += v0.y; c0.z += v0.z; c0.w += v0.w;
        c1.x += v1.x; c1.y += v1.y; c1.z += v1.z; c1.w += v1.w;
        c2.x += v2.x; c2.y += v2.y; c2.z += v2.z; c2.w += v2.w;
        c3.x += v3.x; c3.y += v3.y; c3.z += v3.z; c3.w += v3.w;
        float rs = v0.x + v0.y + v0.z + v0.w + v1.x + v1.y + v1.z + v1.w
                 + v2.x + v2.y + v2.z + v2.w + v3.x + v3.y + v3.z + v3.w;
#pragma unroll
        for (int o = 16; o > 0; o >>= 1) rs += __shfl_down_sync(0xffffffffu, rs, o);
        if ((t & 31) == 0) atomicAdd(&g_row[r * cNU + n0 + i], rs);
    }
    float* col = g_col + r * cNV;
    int c = 4 * t;
    atomicAdd(&col[c+0],    c0.x); atomicAdd(&col[c+1],    c0.y);
    atomicAdd(&col[c+2],    c0.z); atomicAdd(&col[c+3],    c0.w);
    atomicAdd(&col[c+1024], c1.x); atomicAdd(&col[c+1025], c1.y);
    atomicAdd(&col[c+1026], c1.z); atomicAdd(&col[c+1027], c1.w);
    atomicAdd(&col[c+2048], c2.x); atomicAdd(&col[c+2049], c2.y);
    atomicAdd(&col[c+2050], c2.z); atomicAdd(&col[c+2051], c2.w);
    atomicAdd(&col[c+3072], c3.x); atomicAdd(&col[c+3073], c3.y);
    atomicAdd(&col[c+3074], c3.z); atomicAdd(&col[c+3075], c3.w);
}

// ---------------- feature GEMM on tensor cores (fp16 3-term split) ----------
__global__ void __launch_bounds__(256, 2) kfeat(const float* __restrict__ u_feat,
                                                const float* __restrict__ v_feat) {
    __shared__ __align__(1024) unsigned char sm[2][24576];
    const int sid = blockIdx.y;
    const bool uside = sid < cR;
    const int r = uside ? sid : sid - cR;
    const float* F = uside ? u_feat : v_feat;
    const u32* Wh = g_Wh + (size_t)sid * 8192;
    const u32* Wl = g_Wl + (size_t)sid * 8192;
    const float* sraw = (uside ? g_row : g_col) + r * 4096;
    const size_t ib = (size_t)(uside ? 5 + r : r) * 131072;
    const int t = threadIdx.x;
    const int wid = t >> 5, lane = t & 31;
    const int mw = (wid & 3) * 32;
    const int nw = (wid >> 2) * 32;
    const int outb = blockIdx.x * 128;
    const u32 sb = smem_u32(sm);

    const int bk_ = t >> 3, bc4 = (t & 7) * 4;
    const u32 offB = swzB(bk_, (t & 7) * 8);

    float acc[8][4];
#pragma unroll
    for (int j = 0; j < 8; j++)
#pragma unroll
        for (int q = 0; q < 4; q++) acc[j][q] = 0.f;

    float4 ra[4];
    auto ldgF = [&](int c) {
        const float4* ap =
            (const float4*)(F + (size_t)(outb + (t >> 1)) * cD + c * 32 + (t & 1) * 16);
        ra[0] = ap[0]; ra[1] = ap[1]; ra[2] = ap[2]; ra[3] = ap[3];
    };
    auto stsF = [&](int b) {
        unsigned char* base = sm[b];
        const float* f = (const float*)ra;
        int row = t >> 1, kk = (t & 1) * 16;
#pragma unroll
        for (int j = 0; j < 8; j++) {
            u32 h, l; split2h(f[2 * j], f[2 * j + 1], h, l);
            u32 off = swzA_nt(row, kk + 2 * j);
            *(u32*)(base + off) = h;
            *(u32*)(base + 8192 + off) = l;
        }
    };
    auto cpW = [&](int c, int b) {
        const u32 sbuf = sb + b * 24576;
        size_t gofs = (size_t)(c * 32 + bk_) * 32 + bc4;
        CP_ASYNC16(sbuf + 16384 + offB, Wh + gofs);
        CP_ASYNC16(sbuf + 20480 + offB, Wl + gofs);
        CP_COMMIT();
    };

    ldgF(0);
    cpW(0, 0);
    stsF(0);
    ldgF(1);

    for (int c = 0; c < 8; c++) {
        CP_WAIT0();
        __syncthreads();
        if (c + 1 < 8) {
            stsF((c + 1) & 1);
            cpW(c + 1, (c + 1) & 1);
            if (c + 2 < 8) ldgF(c + 2);
        }
        const u32 sbuf = sb + (c & 1) * 24576;
#pragma unroll
        for (int s = 0; s < 2; s++) {
            const int k0s = s * 16;
            u32 ah[2][4], al[2][4];
            {
                int arow = mw + (lane & 15);
                int acol = (lane >> 4) * 8 + k0s;
                u32 o0 = swzA_nt(arow, acol), o1 = swzA_nt(arow + 16, acol);
                LDSM4(ah[0], sbuf + o0);
                LDSM4(ah[1], sbuf + o1);
                LDSM4(al[0], sbuf + 8192 + o0);
                LDSM4(al[1], sbuf + 8192 + o1);
            }
            u32 bh[2][4], bl[2][4];
            {
                int krow = k0s + (lane & 15);
#pragma unroll
                for (int g = 0; g < 2; g++) {
                    u32 off = swzB(krow, nw + g * 16 + (lane >> 4) * 8);
                    LDSM4T(bh[g], sbuf + 16384 + off);
                    LDSM4T(bl[g], sbuf + 20480 + off);
                }
            }
#pragma unroll
            for (int mi = 0; mi < 2; mi++)
#pragma unroll
                for (int g = 0; g < 2; g++)
#pragma unroll
                    for (int half = 0; half < 2; half++) {
                        const int j = mi * 4 + g * 2 + half;
                        MMA_F16(acc[j], ah[mi], bh[g][2 * half], bh[g][2 * half + 1]);
                        MMA_F16(acc[j], al[mi], bh[g][2 * half], bh[g][2 * half + 1]);
                        MMA_F16(acc[j], ah[mi], bl[g][2 * half], bl[g][2 * half + 1]);
                    }
        }
    }

    const int g2 = lane >> 2, t2 = lane & 3;
#pragma unroll
    for (int mi = 0; mi < 2; mi++) {
        const int row0 = outb + mw + mi * 16 + g2;
        const int row1 = row0 + 8;
        const float s0 = invs(sraw[row0]);
        const float s1 = invs(sraw[row1]);
#pragma unroll
        for (int ni = 0; ni < 4; ni++) {
            const int j = mi * 4 + ni;
            const int pair = (nw + ni * 8 + 2 * t2) >> 1;
            g_Bhi[ib + (size_t)row0 * 32 + pair] = pack2h(s0 * acc[j][0], s0 * acc[j][1]);
            g_Bhi[ib + (size_t)row1 * 32 + pair] = pack2h(s1 * acc[j][2], s1 * acc[j][3]);
        }
    }
}

// ---------------- main contraction: single-fp16, 4-stage pipeline ----------
// smem per stage (20 KB): A @0 (16K), B @16384 (4K); 4 stages = 80 KB
template <bool TRANS>
__device__ __forceinline__ void kmain_body(unsigned char (*sm)[20480],
                                           int r, int tileb, int ks) {
    const int t = threadIdx.x;
    const int wid = t >> 5, lane = t & 31;
    const int mw = (wid & 3) * 64;
    const int nw = (wid >> 2) * 32;
    const float* sraw = (TRANS ? g_col : g_row) + r * 4096;
    const int sr = (TRANS ? 5 : 0) + r;
    const u32* imgh = g_Bhi + (size_t)sr * 131072;
    const char* S16r = (const char*)(g_S16 + (size_t)r * cNU * (cNV / 2));
    const int kbase = ks * KSLICE;
    const u32 sb = smem_u32(sm);

    const int bk_ = t >> 3, bc4 = (t & 7) * 4;
    const u32 offB = swzB(bk_, (t & 7) * 8);

    float acc[16][4];
#pragma unroll
    for (int j = 0; j < 16; j++)
#pragma unroll
        for (int q = 0; q < 4; q++) acc[j][q] = 0.f;

    auto cpAB = [&](int c, int b) {
        const u32 sbuf = sb + b * 20480;
        const int kk0 = kbase + c * 32;
        if (!TRANS) {
#pragma unroll
            for (int q = 0; q < 4; q++) {
                int idx = t + q * 256;
                int row = idx >> 2, c16 = idx & 3;
                CP_ASYNC16(sbuf + sw_nt((u32)(row * 64 + c16 * 16)),
                           S16r + (size_t)(tileb + row) * 8192 + kk0 * 2 + c16 * 16);
            }
        } else {
#pragma unroll
            for (int q = 0; q < 4; q++) {
                int idx = t + q * 256;
                int krow = idx >> 5, c16 = idx & 31;
                CP_ASYNC16(sbuf + sw_t2((u32)(krow * 512 + c16 * 16)),
                           S16r + (size_t)(kk0 + krow) * 8192 + tileb * 2 + c16 * 16);
            }
        }
        CP_ASYNC16(sbuf + 16384 + offB, imgh + (size_t)(kk0 + bk_) * 32 + bc4);
        CP_COMMIT();
    };

    cpAB(0, 0);
    cpAB(1, 1);
    cpAB(2, 2);
    for (int c = 0; c < NC; c++) {
        if (c <= NC - 3)      { CP_WAIT2(); }
        else if (c == NC - 2) { CP_WAIT1(); }
        else                  { CP_WAIT0(); }
        __syncthreads();
        const u32 sbuf = sb + (c & 3) * 20480;
#pragma unroll
        for (int s = 0; s < 2; s++) {
            const int k0s = s * 16;
            u32 a[4][4];
            if (!TRANS) {
                int arow = mw + (lane & 15);
                int acol = (lane >> 4) * 8 + k0s;
#pragma unroll
                for (int mi = 0; mi < 4; mi++)
                    LDSM4(a[mi], sbuf + sw_nt((u32)((arow + 16 * mi) * 64 + acol * 2)));
            } else {
                int krow = k0s + (lane & 7) + ((lane >> 4) << 3);
                int col0 = mw + ((lane >> 3) & 1) * 8;
#pragma unroll
                for (int mi = 0; mi < 4; mi++)
                    LDSM4T(a[mi], sbuf + sw_t2((u32)(krow * 512 + (col0 + 16 * mi) * 2)));
            }
            u32 bh[2][4];
            {
                int krow = k0s + (lane & 15);
#pragma unroll
                for (int g = 0; g < 2; g++)
                    LDSM4T(bh[g], sbuf + 16384 + swzB(krow, nw + g * 16 + (lane >> 4) * 8));
            }
#pragma unroll
            for (int mi = 0; mi < 4; mi++)
#pragma unroll
                for (int g = 0; g < 2; g++)
#pragma unroll
                    for (int half = 0; half < 2; half++) {
                        const int j = mi * 4 + g * 2 + half;
                        MMA_F16(acc[j], a[mi], bh[g][2 * half], bh[g][2 * half + 1]);
                    }
        }
        __syncthreads();
        if (c + 3 < NC) cpAB(c + 3, (c + 3) & 3);
    }

    // epilogue: scale + vectorized atomic accumulate (red.v2.f32)
    const int g2 = lane >> 2, t2 = lane & 3;
    float* Aout = TRANS ? g_Av : g_Au;
#pragma unroll
    for (int mi = 0; mi < 4; mi++) {
        const int row0 = tileb + mw + mi * 16 + g2;
        const int row1 = row0 + 8;
        const float s0 = invs(sraw[row0]) * 0.00390625f;  // undo 256x image pre-scale
        const float s1 = invs(sraw[row1]) * 0.00390625f;
#pragma unroll
        for (int ni = 0; ni < 4; ni++) {
            const int j = mi * 4 + ni;
            const int col = nw + ni * 8 + 2 * t2;
            REDV2(&Aout[(size_t)row0 * 64 + col], s0 * acc[j][0], s0 * acc[j][1]);
            REDV2(&Aout[(size_t)row1 * 64 + col], s1 * acc[j][2], s1 * acc[j][3]);
        }
    }
}

__global__ void __launch_bounds__(256, 2) kmain_all() {
    __shared__ __align__(1024) unsigned char sm[4][20480];
    const int z = blockIdx.z;
    const int side = z / cR, r = z % cR;
    const int tileb = blockIdx.x * TM;
    const int ks = blockIdx.y;
    if (side == 0) kmain_body<false>(sm, r, tileb, ks);
    else           kmain_body<true >(sm, r, tileb, ks);
}

__global__ void kout(const int* __restrict__ u, const int* __restrict__ v,
                     const float* __restrict__ bias, float* __restrict__ out) {
    int i = blockIdx.x * blockDim.x + threadIdx.x;
    if (i >= 2 * cB * cH) return;
    int h = i & 63;
    float bv = bias[h];
    float z;
    if (i < cB * cH) {
        int b = i >> 6;
        z = g_Au[(size_t)u[b] * cH + h] + bv;
    } else {
        int b = (i - cB * cH) >> 6;
        z = g_Av[(size_t)v[b] * cH + h] + bv;
    }
    out[i] = z > 0.f ? z : 0.f;
}

// ---------------- launch ----------------
extern "C" void kernel_launch(void* const* d_in, const int* in_sizes, int n_in,
                              void* d_out, int out_size) {
    const float* u_feat   = (const float*)d_in[0];
    const float* v_feat   = (const float*)d_in[1];
    const int*   u        = (const int*)d_in[2];
    const int*   v        = (const int*)d_in[3];
    const float* support  = (const float*)d_in[4];
    const float* u_weight = (const float*)d_in[5];
    const float* v_weight = (const float*)d_in[6];
    const float* u_bias   = (const float*)d_in[7];
    float* out = (float*)d_out;

    kinit<<<1024, 256>>>(u_weight, v_weight);
    ksums<<<640, 256>>>(support);
    kfeat<<<dim3(32, 10), 256>>>(u_feat, v_feat);
    kmain_all<<<dim3(cNU / TM, KSPLIT, 2 * cR), 256>>>();
    kout<<<2048, 256>>>(u, v, u_bias, out);
}

// round 17
// speedup vs baseline: 2.1436x; 1.0035x over previous
#include <cuda_runtime.h>
#include <cuda_fp16.h>

typedef unsigned long long ull;
typedef unsigned int u32;

constexpr int cNU = 4096, cNV = 4096, cD = 256, cH = 64, cR = 5, cB = 4096;
constexpr int KSPLIT = 4;
constexpr int KSLICE = 4096 / KSPLIT; // 1024
constexpr int BK = 128;
constexpr int NC = KSLICE / BK;       // 8 chunks per block
constexpr int TM = 128;               // block tile rows

// ---------------- device scratch ----------------
__device__ float g_row[cR * cNU];
__device__ float g_col[cR * cNV];
// fp16 image of support (row-major, same layout as S): [r][n][m], 2 fp16 per u32
__device__ u32 g_S16[(size_t)cR * cNU * cNV / 2];
// fp16 hi/lo images of cumsum'd weights * 256: [sid(0..9)][k=256][32 u32 along h]
__device__ u32 g_Wh[10 * 8192];
__device__ u32 g_Wl[10 * 8192];
// fp16 image (scale*256 folded): side 0 = tv-side (A_u), side 1 = tu-side (A_v)
__device__ u32 g_Bhi[2 * 5 * 131072];
__device__ float g_Au[cNU * cH];
__device__ float g_Av[cNV * cH];

// ---------------- helpers ----------------
__device__ __forceinline__ u32 smem_u32(const void* p) {
    u32 a;
    asm("{ .reg .u64 t; cvta.to.shared.u64 t, %1; cvt.u32.u64 %0, t; }" : "=r"(a) : "l"(p));
    return a;
}
__device__ __forceinline__ void split2h(float x0, float x1, u32 &h, u32 &l) {
    __half2 hh = __float22half2_rn(make_float2(x0, x1));
    float2 bk = __half22float2(hh);
    __half2 ll = __float22half2_rn(make_float2(x0 - bk.x, x1 - bk.y));
    h = *(u32*)&hh;
    l = *(u32*)&ll;
}
__device__ __forceinline__ u32 pack2h(float x0, float x1) {
    __half2 hh = __float22half2_rn(make_float2(x0, x1));
    return *(u32*)&hh;
}
__device__ __forceinline__ float invs(float x) {
    return x > 0.f ? rsqrtf(x) : 0.f;
}

#define LDSM4(r, addr) \
    asm volatile("ldmatrix.sync.aligned.m8n8.x4.shared.b16 {%0,%1,%2,%3}, [%4];" \
                 : "=r"((r)[0]), "=r"((r)[1]), "=r"((r)[2]), "=r"((r)[3]) : "r"(addr))
#define LDSM4T(r, addr) \
    asm volatile("ldmatrix.sync.aligned.m8n8.x4.trans.shared.b16 {%0,%1,%2,%3}, [%4];" \
                 : "=r"((r)[0]), "=r"((r)[1]), "=r"((r)[2]), "=r"((r)[3]) : "r"(addr))
#define MMA_F16(c, a, b0, b1) \
    asm volatile("mma.sync.aligned.m16n8k16.row.col.f32.f16.f16.f32 " \
                 "{%0,%1,%2,%3}, {%4,%5,%6,%7}, {%8,%9}, {%0,%1,%2,%3};" \
                 : "+f"((c)[0]), "+f"((c)[1]), "+f"((c)[2]), "+f"((c)[3]) \
                 : "r"((a)[0]), "r"((a)[1]), "r"((a)[2]), "r"((a)[3]), "r"(b0), "r"(b1))
#define CP_ASYNC16(smaddr, gptr) \
    asm volatile("cp.async.ca.shared.global [%0], [%1], 16;" :: "r"(smaddr), "l"(gptr))
#define CP_COMMIT() asm volatile("cp.async.commit_group;" ::: "memory")
#define CP_WAIT0()  asm volatile("cp.async.wait_group 0;" ::: "memory")
#define CP_WAIT1()  asm volatile("cp.async.wait_group 1;" ::: "memory")
#define REDV2(addr, x, y) \
    asm volatile("red.global.add.v2.f32 [%0], {%1, %2};" :: "l"(addr), "f"(x), "f"(y) : "memory")

// smem swizzles (byte offsets; writer and ldmatrix reader use the same formula)
__device__ __forceinline__ u32 sw_nt(u32 o)  { return o ^ ((o >> 3) & 0x30); } // 64B rows
__device__ __forceinline__ u32 sw256(u32 o)  { return o ^ ((o >> 4) & 0x70); } // 256B rows
__device__ __forceinline__ u32 swzA_nt(int row, int k) { return sw_nt((u32)(row * 64 + k * 2)); }
__device__ __forceinline__ u32 swzB(int k, int n) {      // 128B rows
    u32 o = (u32)(k * 128 + n * 2); return o ^ ((o >> 3) & 0x70);
}

// ---------------- tiny kernels ----------------
__global__ void kinit(const float* __restrict__ uw, const float* __restrict__ vw) {
    int i = blockIdx.x * blockDim.x + threadIdx.x;
    if (i < cNU * cH) { g_Au[i] = 0.f; g_Av[i] = 0.f; }
    if (i < cR * cNU) { g_row[i] = 0.f; g_col[i] = 0.f; }
    if (i < cD * cH / 2) {          // 8192 h-pairs
        int k = i >> 5, hp = i & 31;
        float a0 = 0.f, a1 = 0.f, b0 = 0.f, b1 = 0.f;
#pragma unroll
        for (int r = 0; r < cR; r++) {
            a0 += uw[r * cD * cH + k * cH + 2 * hp];
            a1 += uw[r * cD * cH + k * cH + 2 * hp + 1];
            b0 += vw[r * cD * cH + k * cH + 2 * hp];
            b1 += vw[r * cD * cH + k * cH + 2 * hp + 1];
            u32 h, l;
            split2h(256.f * a0, 256.f * a1, h, l);
            g_Wh[(size_t)r * 8192 + k * 32 + hp] = h;
            g_Wl[(size_t)r * 8192 + k * 32 + hp] = l;
            split2h(256.f * b0, 256.f * b1, h, l);
            g_Wh[(size_t)(5 + r) * 8192 + k * 32 + hp] = h;
            g_Wl[(size_t)(5 + r) * 8192 + k * 32 + hp] = l;
        }
    }
}

// row/col sums of support + write fp16 image of S (one pass over S)
__global__ void __launch_bounds__(256) ksums(const float* __restrict__ S) {
    constexpr int RPC = 32;
    int blk = blockIdx.x;
    int r  = blk / (cNU / RPC);
    int n0 = (blk % (cNU / RPC)) * RPC;
    const float* base = S + ((size_t)r * cNU + n0) * cNV;
    int t = threadIdx.x;
    float4 c0 = {0,0,0,0}, c1 = c0, c2 = c0, c3 = c0;
    for (int i = 0; i < RPC; i++) {
        const float4* rp = (const float4*)(base + (size_t)i * cNV);
        float4 v0 = rp[t], v1 = rp[t + 256], v2 = rp[t + 512], v3 = rp[t + 768];
        u32* s16 = g_S16 + ((size_t)r * cNU + n0 + i) * (cNV / 2);
        *(uint2*)(s16 + 2 * t)        = make_uint2(pack2h(v0.x, v0.y), pack2h(v0.z, v0.w));
        *(uint2*)(s16 + 2 * t + 512)  = make_uint2(pack2h(v1.x, v1.y), pack2h(v1.z, v1.w));
        *(uint2*)(s16 + 2 * t + 1024) = make_uint2(pack2h(v2.x, v2.y), pack2h(v2.z, v2.w));
        *(uint2*)(s16 + 2 * t + 1536) = make_uint2(pack2h(v3.x, v3.y), pack2h(v3.z, v3.w));
        c0.x += v0.x; c0.y += v0.y; c0.z += v0.z; c0.w += v0.w;
        c1.x += v1.x; c1.y += v1.y; c1.z += v1.z; c1.w += v1.w;
        c2.x += v2.x; c2.y += v2.y; c2.z += v2.z; c2.w += v2.w;
        c3.x += v3.x; c3.y += v3.y; c3.z += v3.z; c3.w += v3.w;
        float rs = v0.x + v0.y + v0.z + v0.w + v1.x + v1.y + v1.z + v1.w
                 + v2.x + v2.y + v2.z + v2.w + v3.x + v3.y + v3.z + v3.w;
#pragma unroll
        for (int o = 16; o > 0; o >>= 1) rs += __shfl_down_sync(0xffffffffu, rs, o);
        if ((t & 31) == 0) atomicAdd(&g_row[r * cNU + n0 + i], rs);
    }
    float* col = g_col + r * cNV;
    int c = 4 * t;
    atomicAdd(&col[c+0],    c0.x); atomicAdd(&col[c+1],    c0.y);
    atomicAdd(&col[c+2],    c0.z); atomicAdd(&col[c+3],    c0.w);
    atomicAdd(&col[c+1024], c1.x); atomicAdd(&col[c+1025], c1.y);
    atomicAdd(&col[c+1026], c1.z); atomicAdd(&col[c+1027], c1.w);
    atomicAdd(&col[c+2048], c2.x); atomicAdd(&col[c+2049], c2.y);
    atomicAdd(&col[c+2050], c2.z); atomicAdd(&col[c+2051], c2.w);
    atomicAdd(&col[c+3072], c3.x); atomicAdd(&col[c+3073], c3.y);
    atomicAdd(&col[c+3074], c3.z); atomicAdd(&col[c+3075], c3.w);
}

// ---------------- feature GEMM on tensor cores (fp16 3-term split) ----------
__global__ void __launch_bounds__(256, 2) kfeat(const float* __restrict__ u_feat,
                                                const float* __restrict__ v_feat) {
    __shared__ __align__(1024) unsigned char sm[2][24576];
    const int sid = blockIdx.y;
    const bool uside = sid < cR;
    const int r = uside ? sid : sid - cR;
    const float* F = uside ? u_feat : v_feat;
    const u32* Wh = g_Wh + (size_t)sid * 8192;
    const u32* Wl = g_Wl + (size_t)sid * 8192;
    const float* sraw = (uside ? g_row : g_col) + r * 4096;
    const size_t ib = (size_t)(uside ? 5 + r : r) * 131072;
    const int t = threadIdx.x;
    const int wid = t >> 5, lane = t & 31;
    const int mw = (wid & 3) * 32;
    const int nw = (wid >> 2) * 32;
    const int outb = blockIdx.x * 128;
    const u32 sb = smem_u32(sm);

    const int bk_ = t >> 3, bc4 = (t & 7) * 4;
    const u32 offB = swzB(bk_, (t & 7) * 8);

    float acc[8][4];
#pragma unroll
    for (int j = 0; j < 8; j++)
#pragma unroll
        for (int q = 0; q < 4; q++) acc[j][q] = 0.f;

    float4 ra[4];
    auto ldgF = [&](int c) {
        const float4* ap =
            (const float4*)(F + (size_t)(outb + (t >> 1)) * cD + c * 32 + (t & 1) * 16);
        ra[0] = ap[0]; ra[1] = ap[1]; ra[2] = ap[2]; ra[3] = ap[3];
    };
    auto stsF = [&](int b) {
        unsigned char* base = sm[b];
        const float* f = (const float*)ra;
        int row = t >> 1, kk = (t & 1) * 16;
#pragma unroll
        for (int j = 0; j < 8; j++) {
            u32 h, l; split2h(f[2 * j], f[2 * j + 1], h, l);
            u32 off = swzA_nt(row, kk + 2 * j);
            *(u32*)(base + off) = h;
            *(u32*)(base + 8192 + off) = l;
        }
    };
    auto cpW = [&](int c, int b) {
        const u32 sbuf = sb + b * 24576;
        size_t gofs = (size_t)(c * 32 + bk_) * 32 + bc4;
        CP_ASYNC16(sbuf + 16384 + offB, Wh + gofs);
        CP_ASYNC16(sbuf + 20480 + offB, Wl + gofs);
        CP_COMMIT();
    };

    ldgF(0);
    cpW(0, 0);
    stsF(0);
    ldgF(1);

    for (int c = 0; c < 8; c++) {
        CP_WAIT0();
        __syncthreads();
        if (c + 1 < 8) {
            stsF((c + 1) & 1);
            cpW(c + 1, (c + 1) & 1);
            if (c + 2 < 8) ldgF(c + 2);
        }
        const u32 sbuf = sb + (c & 1) * 24576;
#pragma unroll
        for (int s = 0; s < 2; s++) {
            const int k0s = s * 16;
            u32 ah[2][4], al[2][4];
            {
                int arow = mw + (lane & 15);
                int acol = (lane >> 4) * 8 + k0s;
                u32 o0 = swzA_nt(arow, acol), o1 = swzA_nt(arow + 16, acol);
                LDSM4(ah[0], sbuf + o0);
                LDSM4(ah[1], sbuf + o1);
                LDSM4(al[0], sbuf + 8192 + o0);
                LDSM4(al[1], sbuf + 8192 + o1);
            }
            u32 bh[2][4], bl[2][4];
            {
                int krow = k0s + (lane & 15);
#pragma unroll
                for (int g = 0; g < 2; g++) {
                    u32 off = swzB(krow, nw + g * 16 + (lane >> 4) * 8);
                    LDSM4T(bh[g], sbuf + 16384 + off);
                    LDSM4T(bl[g], sbuf + 20480 + off);
                }
            }
#pragma unroll
            for (int mi = 0; mi < 2; mi++)
#pragma unroll
                for (int g = 0; g < 2; g++)
#pragma unroll
                    for (int half = 0; half < 2; half++) {
                        const int j = mi * 4 + g * 2 + half;
                        MMA_F16(acc[j], ah[mi], bh[g][2 * half], bh[g][2 * half + 1]);
                        MMA_F16(acc[j], al[mi], bh[g][2 * half], bh[g][2 * half + 1]);
                        MMA_F16(acc[j], ah[mi], bl[g][2 * half], bl[g][2 * half + 1]);
                    }
        }
    }

    const int g2 = lane >> 2, t2 = lane & 3;
#pragma unroll
    for (int mi = 0; mi < 2; mi++) {
        const int row0 = outb + mw + mi * 16 + g2;
        const int row1 = row0 + 8;
        const float s0 = invs(sraw[row0]);
        const float s1 = invs(sraw[row1]);
#pragma unroll
        for (int ni = 0; ni < 4; ni++) {
            const int j = mi * 4 + ni;
            const int pair = (nw + ni * 8 + 2 * t2) >> 1;
            g_Bhi[ib + (size_t)row0 * 32 + pair] = pack2h(s0 * acc[j][0], s0 * acc[j][1]);
            g_Bhi[ib + (size_t)row1 * 32 + pair] = pack2h(s1 * acc[j][2], s1 * acc[j][3]);
        }
    }
}

// ---------------- main contraction: TM=128, BK=128, 2-stage pipeline ----------
// smem per stage (48 KB): A @0 (32K, 256B rows), B @32768 (16K, 128B rows)
template <bool TRANS>
__device__ __forceinline__ void kmain_body(unsigned char (*sm)[49152],
                                           int r, int tileb, int ks) {
    const int t = threadIdx.x;
    const int wid = t >> 5, lane = t & 31;
    const int mw = (wid & 3) * 32;      // 4 M-warps of 32 rows
    const int nw = (wid >> 2) * 32;     // 2 N-warps of 32 cols
    const float* sraw = (TRANS ? g_col : g_row) + r * 4096;
    const int sr = (TRANS ? 5 : 0) + r;
    const u32* imgh = g_Bhi + (size_t)sr * 131072;
    const char* S16r = (const char*)(g_S16 + (size_t)r * cNU * (cNV / 2));
    const int kbase = ks * KSLICE;
    const u32 sb = smem_u32(sm);

    float acc[8][4];
#pragma unroll
    for (int j = 0; j < 8; j++)
#pragma unroll
        for (int q = 0; q < 4; q++) acc[j][q] = 0.f;

    auto cpAB = [&](int c, int b) {
        const u32 sbuf = sb + b * 49152;
        const int kk0 = kbase + c * BK;
        // A tile: 128 x 128 fp16 = 32 KB, 256B rows (row=output row or k-row)
#pragma unroll
        for (int q = 0; q < 8; q++) {
            int idx = t + q * 256;
            int row = idx >> 4, seg = idx & 15;
            const char* gp = !TRANS
                ? S16r + (size_t)(tileb + row) * 8192 + kk0 * 2 + seg * 16
                : S16r + (size_t)(kk0 + row) * 8192 + tileb * 2 + seg * 16;
            CP_ASYNC16(sbuf + sw256((u32)(row * 256 + seg * 16)), gp);
        }
        // B tile: 128 k x 64 h fp16 = 16 KB, 128B rows
#pragma unroll
        for (int q = 0; q < 4; q++) {
            int idx = t + q * 256;
            int krow = idx >> 3, seg = idx & 7;
            CP_ASYNC16(sbuf + 32768 + swzB(krow, seg * 8),
                       imgh + (size_t)(kk0 + krow) * 32 + seg * 4);
        }
        CP_COMMIT();
    };

    cpAB(0, 0);
    for (int c = 0; c < NC; c++) {
        if (c + 1 < NC) { cpAB(c + 1, (c + 1) & 1); CP_WAIT1(); }
        else            { CP_WAIT0(); }
        __syncthreads();
        const u32 sbuf = sb + (c & 1) * 49152;
#pragma unroll
        for (int s = 0; s < 8; s++) {
            const int k0s = s * 16;
            u32 a[2][4];
            if (!TRANS) {
                int arow = mw + (lane & 15);
                int acol = (lane >> 4) * 8 + k0s;
                LDSM4(a[0], sbuf + sw256((u32)(arow * 256 + acol * 2)));
                LDSM4(a[1], sbuf + sw256((u32)((arow + 16) * 256 + acol * 2)));
            } else {
                int krow = k0s + (lane & 7) + ((lane >> 4) << 3);
                int col0 = mw + ((lane >> 3) & 1) * 8;
                LDSM4T(a[0], sbuf + sw256((u32)(krow * 256 + col0 * 2)));
                LDSM4T(a[1], sbuf + sw256((u32)(krow * 256 + (col0 + 16) * 2)));
            }
            u32 bh[2][4];
            {
                int krow = k0s + (lane & 15);
                LDSM4T(bh[0], sbuf + 32768 + swzB(krow, nw + (lane >> 4) * 8));
                LDSM4T(bh[1], sbuf + 32768 + swzB(krow, nw + 16 + (lane >> 4) * 8));
            }
#pragma unroll
            for (int mi = 0; mi < 2; mi++)
#pragma unroll
                for (int g = 0; g < 2; g++)
#pragma unroll
                    for (int half = 0; half < 2; half++) {
                        const int j = mi * 4 + g * 2 + half;
                        MMA_F16(acc[j], a[mi], bh[g][2 * half], bh[g][2 * half + 1]);
                    }
        }
        __syncthreads();
    }

    // epilogue: scale + vectorized atomic accumulate (red.v2.f32)
    const int g2 = lane >> 2, t2 = lane & 3;
    float* Aout = TRANS ? g_Av : g_Au;
#pragma unroll
    for (int mi = 0; mi < 2; mi++) {
        const int row0 = tileb + mw + mi * 16 + g2;
        const int row1 = row0 + 8;
        const float s0 = invs(sraw[row0]) * 0.00390625f;  // undo 256x image pre-scale
        const float s1 = invs(sraw[row1]) * 0.00390625f;
#pragma unroll
        for (int ni = 0; ni < 4; ni++) {
            const int j = mi * 4 + ni;
            const int col = nw + ni * 8 + 2 * t2;
            REDV2(&Aout[(size_t)row0 * 64 + col], s0 * acc[j][0], s0 * acc[j][1]);
            REDV2(&Aout[(size_t)row1 * 64 + col], s1 * acc[j][2], s1 * acc[j][3]);
        }
    }
}

__global__ void __launch_bounds__(256, 2) kmain_all() {
    __shared__ __align__(1024) unsigned char sm[2][49152];
    const int z = blockIdx.z;
    const int side = z / cR, r = z % cR;
    const int tileb = blockIdx.x * TM;
    const int ks = blockIdx.y;
    if (side == 0) kmain_body<false>(sm, r, tileb, ks);
    else           kmain_body<true >(sm, r, tileb, ks);
}

__global__ void kout(const int* __restrict__ u, const int* __restrict__ v,
                     const float* __restrict__ bias, float* __restrict__ out) {
    int i = blockIdx.x * blockDim.x + threadIdx.x;
    if (i >= 2 * cB * cH) return;
    int h = i & 63;
    float bv = bias[h];
    float z;
    if (i < cB * cH) {
        int b = i >> 6;
        z = g_Au[(size_t)u[b] * cH + h] + bv;
    } else {
        int b = (i - cB * cH) >> 6;
        z = g_Av[(size_t)v[b] * cH + h] + bv;
    }
    out[i] = z > 0.f ? z : 0.f;
}

// ---------------- launch ----------------
extern "C" void kernel_launch(void* const* d_in, const int* in_sizes, int n_in,
                              void* d_out, int out_size) {
    const float* u_feat   = (const float*)d_in[0];
    const float* v_feat   = (const float*)d_in[1];
    const int*   u        = (const int*)d_in[2];
    const int*   v        = (const int*)d_in[3];
    const float* support  = (const float*)d_in[4];
    const float* u_weight = (const float*)d_in[5];
    const float* v_weight = (const float*)d_in[6];
    const float* u_bias   = (const float*)d_in[7];
    float* out = (float*)d_out;

    kinit<<<1024, 256>>>(u_weight, v_weight);
    ksums<<<640, 256>>>(support);
    kfeat<<<dim3(32, 10), 256>>>(u_feat, v_feat);
    kmain_all<<<dim3(cNU / TM, KSPLIT, 2 * cR), 256>>>();
    kout<<<2048, 256>>>(u, v, u_bias, out);
}